// round 3
// baseline (speedup 1.0000x reference)
#include <cuda_runtime.h>
#include <cuda_bf16.h>
#include <cstdint>

#define BN_EPS 1e-5f

__device__ float              g_pool[16 * 16 * 256 * 256];
__device__ unsigned char      g_mask[256 * 256];
__device__ int                g_count_i;
__device__ float              g_S[16 * 32];
__device__ unsigned long long g_w1p[27 * 16];    // folded conv1 w, packed {w,w}
__device__ unsigned long long g_w2p[144 * 32];   // folded conv2 w, packed {w,w}
__device__ float              g_bias1[16];
__device__ float              g_bias2[32];

// ---- f32x2 helpers --------------------------------------------------------
__device__ __forceinline__ unsigned long long pk2(float a, float b) {
    unsigned long long r;
    asm("mov.b64 %0, {%1, %2};" : "=l"(r) : "f"(a), "f"(b));
    return r;
}
__device__ __forceinline__ void upk2(unsigned long long v, float& a, float& b) {
    asm("mov.b64 {%0, %1}, %2;" : "=f"(a), "=f"(b) : "l"(v));
}
__device__ __forceinline__ unsigned long long f2fma(unsigned long long a,
                                                    unsigned long long b,
                                                    unsigned long long c) {
    unsigned long long d;
    asm("fma.rn.f32x2 %0, %1, %2, %3;" : "=l"(d) : "l"(a), "l"(b), "l"(c));
    return d;
}

// ---------------------------------------------------------------------------
__global__ void prep_kernel(const float* __restrict__ w1,
                            const float* __restrict__ g1, const float* __restrict__ b1,
                            const float* __restrict__ m1, const float* __restrict__ v1,
                            const float* __restrict__ w2,
                            const float* __restrict__ g2, const float* __restrict__ b2,
                            const float* __restrict__ m2, const float* __restrict__ v2) {
    int t = threadIdx.x;  // 256
    for (int i = t; i < 512; i += 256) g_S[i] = 0.f;
    if (t == 0) g_count_i = 0;
    for (int i = t; i < 16 * 27; i += 256) {
        int co = i / 27, k = i % 27;
        float s = g1[co] * rsqrtf(v1[co] + BN_EPS);
        float w = w1[co * 27 + k] * s;
        g_w1p[k * 16 + co] = pk2(w, w);
    }
    for (int i = t; i < 32 * 144; i += 256) {
        int co = i / 144, k = i % 144;
        float s = g2[co] * rsqrtf(v2[co] + BN_EPS);
        float w = w2[co * 144 + k] * s;
        g_w2p[k * 32 + co] = pk2(w, w);
    }
    if (t < 16) {
        float s = g1[t] * rsqrtf(v1[t] + BN_EPS);
        g_bias1[t] = b1[t] - m1[t] * s;
    }
    if (t < 32) {
        float s = g2[t] * rsqrtf(v2[t] + BN_EPS);
        g_bias2[t] = b2[t] - m2[t] * s;
    }
}

// ---------------------------------------------------------------------------
// K1: conv1(3->16) + BN + ReLU + maxpool2x2.
// 256 threads = 4 channel-groups(4ch) x 64 spatial.
// Thread = 2 pooled px (= 4x2 conv px) x 4 channels. Pooled tile 16x8.
// ---------------------------------------------------------------------------
__global__ __launch_bounds__(256, 2) void k1_kernel(const float* __restrict__ x) {
    __shared__ float              s_x[3 * 18 * 36];   // conv tile 32x16 + halo
    __shared__ unsigned long long s_w[27 * 16];
    __shared__ float              s_b[16];

    int b = blockIdx.z, bx = blockIdx.x, by = blockIdx.y;
    int tid = threadIdx.x;

    for (int i = tid; i < 27 * 16; i += 256) s_w[i] = g_w1p[i];
    if (tid < 16) s_b[tid] = g_bias1[tid];

    int y0 = by * 16 - 1, x0 = bx * 32 - 1;
    for (int i = tid; i < 3 * 18 * 34; i += 256) {
        int cin = i / 612, rem = i % 612, r = rem / 34, c = rem % 34;
        int gy = y0 + r, gx = x0 + c;
        float v = 0.f;
        if ((unsigned)gy < 512u && (unsigned)gx < 512u)
            v = x[((b * 3 + cin) * 512 + gy) * 512 + gx];
        s_x[cin * 648 + r * 36 + c] = v;
    }
    __syncthreads();

    int cog = tid >> 6, sp = tid & 63, ry = sp >> 3, xc = sp & 7;
    // a[ch][convrow r][pair p]: pair p covers conv px (4xc+2p, 4xc+2p+1)
    unsigned long long acc[4][2][2];
#pragma unroll
    for (int c = 0; c < 4; c++)
#pragma unroll
        for (int r = 0; r < 2; r++) { acc[c][r][0] = 0ull; acc[c][r][1] = 0ull; }

#pragma unroll
    for (int cin = 0; cin < 3; cin++) {
        float rv[4][6];  // input rows 2ry .. 2ry+3, cols 4xc .. 4xc+5
#pragma unroll
        for (int j = 0; j < 4; j++) {
            const float* p = s_x + cin * 648 + (2 * ry + j) * 36 + 4 * xc;
            float4 q = *(const float4*)p;
            float2 q2 = *(const float2*)(p + 4);
            rv[j][0] = q.x; rv[j][1] = q.y; rv[j][2] = q.z; rv[j][3] = q.w;
            rv[j][4] = q2.x; rv[j][5] = q2.y;
        }
#pragma unroll
        for (int ky = 0; ky < 3; ky++) {
#pragma unroll
            for (int kx = 0; kx < 3; kx++) {
                const ulonglong2* wv =
                    (const ulonglong2*)(s_w + (cin * 9 + ky * 3 + kx) * 16 + cog * 4);
                ulonglong2 w01 = wv[0], w23 = wv[1];
#pragma unroll
                for (int r = 0; r < 2; r++) {  // conv output row
                    unsigned long long i0 = pk2(rv[r + ky][kx],     rv[r + ky][kx + 1]);
                    unsigned long long i1 = pk2(rv[r + ky][kx + 2], rv[r + ky][kx + 3]);
                    acc[0][r][0] = f2fma(i0, w01.x, acc[0][r][0]);
                    acc[0][r][1] = f2fma(i1, w01.x, acc[0][r][1]);
                    acc[1][r][0] = f2fma(i0, w01.y, acc[1][r][0]);
                    acc[1][r][1] = f2fma(i1, w01.y, acc[1][r][1]);
                    acc[2][r][0] = f2fma(i0, w23.x, acc[2][r][0]);
                    acc[2][r][1] = f2fma(i1, w23.x, acc[2][r][1]);
                    acc[3][r][0] = f2fma(i0, w23.y, acc[3][r][0]);
                    acc[3][r][1] = f2fma(i1, w23.y, acc[3][r][1]);
                }
            }
        }
    }

    int py = by * 8 + ry, px = bx * 16 + 2 * xc;
#pragma unroll
    for (int c = 0; c < 4; c++) {
        int co = cog * 4 + c;
        float bb = s_b[co];
        float2 o;
#pragma unroll
        for (int p = 0; p < 2; p++) {
            float t0, t1, t2, t3;
            upk2(acc[c][0][p], t0, t1);
            upk2(acc[c][1][p], t2, t3);
            float m = fmaxf(fmaxf(t0, t1), fmaxf(t2, t3)) + bb;
            (p == 0 ? o.x : o.y) = fmaxf(m, 0.f);
        }
        *(float2*)(g_pool + (co + b * 16) * 65536 + py * 256 + px) = o;
    }
}

// ---------------------------------------------------------------------------
// K2: conv2(16->32) + BN + ReLU, never materialized.
// 256 threads = 8 channel-groups(4ch) x 32 spatial; warp == one cog.
// Thread = 8 px (4 f32x2 pairs) x 4 channels. Tile 32x8.
// ---------------------------------------------------------------------------
#define K2_IN_BYTES   (16 * 10 * 36 * 4)               // 23040
#define K2_W_OFF      K2_IN_BYTES
#define K2_B_OFF      (K2_W_OFF + 144 * 32 * 8)        // 59904
#define K2_PF_OFF     (K2_B_OFF + 128)                 // 60032
#define K2_SC_OFF     (K2_PF_OFF + 128)                // 60160
#define K2_SMEM_TOTAL (K2_SC_OFF + 7 * 256 * 4)        // 67328

template <int MODE>
__global__ __launch_bounds__(256, 2) void k2_kernel(const float* __restrict__ pf_w,
                                                    const float* __restrict__ pf_b) {
    extern __shared__ char smem[];
    float*              s_in = (float*)smem;                           // [16][10][36]
    unsigned long long* s_w  = (unsigned long long*)(smem + K2_W_OFF); // [144][32]
    float*              s_b  = (float*)(smem + K2_B_OFF);
    float*              s_pf = (float*)(smem + K2_PF_OFF);
    float*              s_sc = (float*)(smem + K2_SC_OFF);             // [7][256]

    int tid = threadIdx.x;
    int b = blockIdx.z, bx = blockIdx.x, by = blockIdx.y;

    for (int i = tid; i < 4608; i += 256) s_w[i] = g_w2p[i];
    if (tid < 32) {
        s_b[tid] = g_bias2[tid];
        if (MODE == 0) s_pf[tid] = pf_w[tid];
    }

    int y0 = by * 8 - 1, x0 = bx * 32 - 1;
    for (int i = tid; i < 5440; i += 256) {  // 16*10*34
        int cin = i / 340, rem = i % 340, r = rem / 34, c = rem % 34;
        int gy = y0 + r, gx = x0 + c;
        float v = 0.f;
        if ((unsigned)gy < 256u && (unsigned)gx < 256u)
            v = g_pool[((b * 16 + cin) * 256 + gy) * 256 + gx];
        s_in[cin * 360 + r * 36 + c] = v;
    }
    __syncthreads();

    int cog = tid >> 5, sp = tid & 31, ry = sp >> 2, xc = sp & 3;
    // acc[ch][pair]: pair p covers px (8xc+2p, 8xc+2p+1)
    unsigned long long acc[4][4];
#pragma unroll
    for (int c = 0; c < 4; c++)
#pragma unroll
        for (int p = 0; p < 4; p++) acc[c][p] = 0ull;

#pragma unroll 4
    for (int cin = 0; cin < 16; cin++) {
        float rw[3][10];
#pragma unroll
        for (int j = 0; j < 3; j++) {
            const float* p = s_in + cin * 360 + (ry + j) * 36 + xc * 8;
            float4 qa = *(const float4*)p;
            float4 qb = *(const float4*)(p + 4);
            float2 qc = *(const float2*)(p + 8);
            rw[j][0] = qa.x; rw[j][1] = qa.y; rw[j][2] = qa.z; rw[j][3] = qa.w;
            rw[j][4] = qb.x; rw[j][5] = qb.y; rw[j][6] = qb.z; rw[j][7] = qb.w;
            rw[j][8] = qc.x; rw[j][9] = qc.y;
        }
#pragma unroll
        for (int ky = 0; ky < 3; ky++) {
#pragma unroll
            for (int kx = 0; kx < 3; kx++) {
                const ulonglong2* wv =
                    (const ulonglong2*)(s_w + (cin * 9 + ky * 3 + kx) * 32 + cog * 4);
                ulonglong2 w01 = wv[0], w23 = wv[1];
                unsigned long long i0 = pk2(rw[ky][kx],     rw[ky][kx + 1]);
                unsigned long long i1 = pk2(rw[ky][kx + 2], rw[ky][kx + 3]);
                unsigned long long i2 = pk2(rw[ky][kx + 4], rw[ky][kx + 5]);
                unsigned long long i3 = pk2(rw[ky][kx + 6], rw[ky][kx + 7]);
                acc[0][0] = f2fma(i0, w01.x, acc[0][0]);
                acc[0][1] = f2fma(i1, w01.x, acc[0][1]);
                acc[0][2] = f2fma(i2, w01.x, acc[0][2]);
                acc[0][3] = f2fma(i3, w01.x, acc[0][3]);
                acc[1][0] = f2fma(i0, w01.y, acc[1][0]);
                acc[1][1] = f2fma(i1, w01.y, acc[1][1]);
                acc[1][2] = f2fma(i2, w01.y, acc[1][2]);
                acc[1][3] = f2fma(i3, w01.y, acc[1][3]);
                acc[2][0] = f2fma(i0, w23.x, acc[2][0]);
                acc[2][1] = f2fma(i1, w23.x, acc[2][1]);
                acc[2][2] = f2fma(i2, w23.x, acc[2][2]);
                acc[2][3] = f2fma(i3, w23.x, acc[2][3]);
                acc[3][0] = f2fma(i0, w23.y, acc[3][0]);
                acc[3][1] = f2fma(i1, w23.y, acc[3][1]);
                acc[3][2] = f2fma(i2, w23.y, acc[3][2]);
                acc[3][3] = f2fma(i3, w23.y, acc[3][3]);
            }
        }
    }

    int y = by * 8 + ry, xg = bx * 32 + xc * 8;

    if (MODE == 0) {
        // partial proposal score over this cog's 4 channels, 8 px
        float sc[8];
#pragma unroll
        for (int p = 0; p < 8; p++) sc[p] = 0.f;
#pragma unroll
        for (int c = 0; c < 4; c++) {
            float bb = s_b[cog * 4 + c], pw = s_pf[cog * 4 + c];
#pragma unroll
            for (int p = 0; p < 4; p++) {
                float v0, v1;
                upk2(acc[c][p], v0, v1);
                sc[2 * p]     += fmaxf(v0 + bb, 0.f) * pw;
                sc[2 * p + 1] += fmaxf(v1 + bb, 0.f) * pw;
            }
        }
        if (cog > 0) {
            float* d = s_sc + (cog - 1) * 256 + sp * 8;
#pragma unroll
            for (int p = 0; p < 8; p++) d[p] = sc[p];
        }
        __syncthreads();
        if (cog == 0) {
            float pb = pf_b[0];
            unsigned char mb[8];
            int cnt = 0;
#pragma unroll
            for (int p = 0; p < 8; p++) {
                float t = sc[p] + pb;
#pragma unroll
                for (int g = 0; g < 7; g++) t += s_sc[g * 256 + sp * 8 + p];
                mb[p] = t > 0.f;
                cnt += mb[p];
            }
            *(unsigned long long*)(g_mask + y * 256 + xg) =
                *(unsigned long long*)mb;
            cnt = __reduce_add_sync(0xffffffffu, cnt);
            if (sp == 0) atomicAdd(&g_count_i, cnt);
        }
    } else {
        unsigned long long mm = *(const unsigned long long*)(g_mask + y * 256 + xg);
        float mk[8];
#pragma unroll
        for (int p = 0; p < 8; p++)
            mk[p] = (float)((unsigned)(mm >> (8 * p)) & 0xffu);
#pragma unroll
        for (int c = 0; c < 4; c++) {
            float bb = s_b[cog * 4 + c];
            float part = 0.f;
#pragma unroll
            for (int p = 0; p < 4; p++) {
                float v0, v1;
                upk2(acc[c][p], v0, v1);
                part += mk[2 * p]     * fmaxf(v0 + bb, 0.f);
                part += mk[2 * p + 1] * fmaxf(v1 + bb, 0.f);
            }
#pragma unroll
            for (int off = 16; off > 0; off >>= 1)
                part += __shfl_xor_sync(0xffffffffu, part, off);
            if (sp == 0) atomicAdd(&g_S[b * 32 + cog * 4 + c], part);
        }
    }
}

// ---------------------------------------------------------------------------
__global__ void k3_kernel(const float* __restrict__ vw, const float* __restrict__ vb,
                          const float* __restrict__ cw, const float* __restrict__ cb,
                          float* __restrict__ out) {
    __shared__ float s_mean[512];
    __shared__ float s_cm[1280];
    int t = threadIdx.x;  // 256
    int cnt = g_count_i;
    float denom = (float)(cnt > 0 ? cnt : 1);
    float frac = cnt > 0 ? 1.f : 0.f;
    for (int i = t; i < 512; i += 256) s_mean[i] = g_S[i] / denom;
    __syncthreads();
    for (int i = t; i < 16 * 80; i += 256) {
        int b = i / 80, k = i % 80;
        float a = vb[k] * frac;
        const float* wm = vw + k * 32;
        const float* mm = s_mean + b * 32;
#pragma unroll
        for (int c = 0; c < 32; c++) a += mm[c] * wm[c];
        s_cm[i] = a;
    }
    __syncthreads();
    for (int i = t; i < 1280; i += 256) {
        int b = i / 80, j = i % 80;
        float a = cb[j];
        const float* w = cw + j * 80;
        const float* m = s_cm + b * 80;
#pragma unroll
        for (int k = 0; k < 80; k++) a += m[k] * w[k];
        out[i] = a;
    }
}

// ---------------------------------------------------------------------------
extern "C" void kernel_launch(void* const* d_in, const int* in_sizes, int n_in,
                              void* d_out, int out_size) {
    const float* x   = (const float*)d_in[0];
    const float* w1  = (const float*)d_in[1];
    const float* g1  = (const float*)d_in[2];
    const float* b1  = (const float*)d_in[3];
    const float* m1  = (const float*)d_in[4];
    const float* v1  = (const float*)d_in[5];
    const float* w2  = (const float*)d_in[6];
    const float* g2  = (const float*)d_in[7];
    const float* b2  = (const float*)d_in[8];
    const float* m2  = (const float*)d_in[9];
    const float* v2  = (const float*)d_in[10];
    const float* pfw = (const float*)d_in[11];
    const float* pfb = (const float*)d_in[12];
    const float* vw  = (const float*)d_in[13];
    const float* vb  = (const float*)d_in[14];
    const float* cw  = (const float*)d_in[15];
    const float* cb  = (const float*)d_in[16];
    float* out = (float*)d_out;

    cudaFuncSetAttribute(k2_kernel<0>, cudaFuncAttributeMaxDynamicSharedMemorySize,
                         K2_SMEM_TOTAL);
    cudaFuncSetAttribute(k2_kernel<1>, cudaFuncAttributeMaxDynamicSharedMemorySize,
                         K2_SMEM_TOTAL);

    prep_kernel<<<1, 256>>>(w1, g1, b1, m1, v1, w2, g2, b2, m2, v2);
    k1_kernel<<<dim3(16, 32, 16), 256>>>(x);
    k2_kernel<0><<<dim3(8, 32, 1), 256, K2_SMEM_TOTAL>>>(pfw, pfb);
    k2_kernel<1><<<dim3(8, 32, 16), 256, K2_SMEM_TOTAL>>>(pfw, pfb);
    k3_kernel<<<1, 256>>>(vw, vb, cw, cb, out);
}

// round 4
// speedup vs baseline: 1.2746x; 1.2746x over previous
#include <cuda_runtime.h>
#include <cuda_bf16.h>
#include <cstdint>

#define BN_EPS 1e-5f

// lanes of every f32x2 = batches (b, b+8), b in 0..7
__device__ float2             g_poolp[8 * 16 * 256 * 256];  // packed pooled features
__device__ unsigned char      g_mask[256 * 256];
__device__ int                g_count_i;
__device__ float              g_S[16 * 32];
__device__ unsigned long long g_w1p[27 * 16];    // folded conv1 w, packed {w,w}
__device__ unsigned long long g_w2p[144 * 32];   // folded conv2 w, packed {w,w}
__device__ float              g_bias1[16];
__device__ float              g_bias2[32];

// ---- f32x2 helpers --------------------------------------------------------
__device__ __forceinline__ unsigned long long pk2(float a, float b) {
    unsigned long long r;
    asm("mov.b64 %0, {%1, %2};" : "=l"(r) : "f"(a), "f"(b));
    return r;
}
__device__ __forceinline__ void upk2(unsigned long long v, float& a, float& b) {
    asm("mov.b64 {%0, %1}, %2;" : "=f"(a), "=f"(b) : "l"(v));
}
__device__ __forceinline__ unsigned long long f2fma(unsigned long long a,
                                                    unsigned long long b,
                                                    unsigned long long c) {
    unsigned long long d;
    asm("fma.rn.f32x2 %0, %1, %2, %3;" : "=l"(d) : "l"(a), "l"(b), "l"(c));
    return d;
}

// ---------------------------------------------------------------------------
__global__ void prep_kernel(const float* __restrict__ w1,
                            const float* __restrict__ g1, const float* __restrict__ b1,
                            const float* __restrict__ m1, const float* __restrict__ v1,
                            const float* __restrict__ w2,
                            const float* __restrict__ g2, const float* __restrict__ b2,
                            const float* __restrict__ m2, const float* __restrict__ v2) {
    int t = threadIdx.x;  // 256
    for (int i = t; i < 512; i += 256) g_S[i] = 0.f;
    if (t == 0) g_count_i = 0;
    for (int i = t; i < 16 * 27; i += 256) {
        int co = i / 27, k = i % 27;
        float s = g1[co] * rsqrtf(v1[co] + BN_EPS);
        float w = w1[co * 27 + k] * s;
        g_w1p[k * 16 + co] = pk2(w, w);
    }
    for (int i = t; i < 32 * 144; i += 256) {
        int co = i / 144, k = i % 144;
        float s = g2[co] * rsqrtf(v2[co] + BN_EPS);
        float w = w2[co * 144 + k] * s;
        g_w2p[k * 32 + co] = pk2(w, w);
    }
    if (t < 16) {
        float s = g1[t] * rsqrtf(v1[t] + BN_EPS);
        g_bias1[t] = b1[t] - m1[t] * s;
    }
    if (t < 32) {
        float s = g2[t] * rsqrtf(v2[t] + BN_EPS);
        g_bias2[t] = b2[t] - m2[t] * s;
    }
}

// ---------------------------------------------------------------------------
// K1: conv1(3->16)+BN+ReLU+maxpool, batch-pair packed in f32x2 lanes.
// Conv tile 32x8 (pooled 16x4). 256 thr = 4 cogs(4ch) x 64 spatial
// (thread = 2x2 conv px = 1 pooled px, both batches in lanes).
// ---------------------------------------------------------------------------
__global__ __launch_bounds__(256, 3) void k1_kernel(const float* __restrict__ x) {
    __shared__ float2             s_x[3 * 10 * 34];   // stride 34 (bank-clean)
    __shared__ unsigned long long s_w[27 * 16];
    __shared__ float              s_b[16];

    int bp = blockIdx.z, bx = blockIdx.x, by = blockIdx.y;
    int tid = threadIdx.x;

    for (int i = tid; i < 27 * 16; i += 256) s_w[i] = g_w1p[i];
    if (tid < 16) s_b[tid] = g_bias1[tid];

    int y0 = by * 8 - 1, x0 = bx * 32 - 1;
    const float* xa = x + (size_t)bp * 3 * 512 * 512;
    const float* xb = x + (size_t)(bp + 8) * 3 * 512 * 512;
    for (int i = tid; i < 3 * 10 * 34; i += 256) {
        int cin = i / 340, rem = i % 340, r = rem / 34, c = rem % 34;
        int gy = y0 + r, gx = x0 + c;
        float a = 0.f, b = 0.f;
        if ((unsigned)gy < 512u && (unsigned)gx < 512u) {
            size_t off = ((size_t)cin * 512 + gy) * 512 + gx;
            a = xa[off];
            b = xb[off];
        }
        s_x[cin * 340 + r * 34 + c] = make_float2(a, b);
    }
    __syncthreads();

    int cog = tid >> 6, sp = tid & 63, ty = sp >> 4, xc = sp & 15;  // ty 0..3, xc 0..15
    unsigned long long acc[4][2][2];  // [ch][conv row r][conv col cx]
#pragma unroll
    for (int c = 0; c < 4; c++)
#pragma unroll
        for (int r = 0; r < 2; r++) { acc[c][r][0] = 0ull; acc[c][r][1] = 0ull; }

#pragma unroll
    for (int cin = 0; cin < 3; cin++) {
        const unsigned long long* base =
            (const unsigned long long*)(s_x + cin * 340) + 2 * xc;
#pragma unroll
        for (int ky = 0; ky < 3; ky++) {
            // rows 2ty+ky (for r=0) and 2ty+ky+1 (for r=1), 4 packed cols each
            const ulonglong2* pA = (const ulonglong2*)(base + (2 * ty + ky) * 34);
            const ulonglong2* pB = (const ulonglong2*)(base + (2 * ty + ky + 1) * 34);
            ulonglong2 qa0 = pA[0], qa1 = pA[1];
            ulonglong2 qb0 = pB[0], qb1 = pB[1];
            unsigned long long rA[4] = {qa0.x, qa0.y, qa1.x, qa1.y};
            unsigned long long rB[4] = {qb0.x, qb0.y, qb1.x, qb1.y};
#pragma unroll
            for (int kx = 0; kx < 3; kx++) {
                const ulonglong2* wv =
                    (const ulonglong2*)(s_w + (cin * 9 + ky * 3 + kx) * 16 + cog * 4);
                ulonglong2 w01 = wv[0], w23 = wv[1];
#pragma unroll
                for (int cx = 0; cx < 2; cx++) {
                    unsigned long long iA = rA[kx + cx];
                    unsigned long long iB = rB[kx + cx];
                    acc[0][0][cx] = f2fma(iA, w01.x, acc[0][0][cx]);
                    acc[0][1][cx] = f2fma(iB, w01.x, acc[0][1][cx]);
                    acc[1][0][cx] = f2fma(iA, w01.y, acc[1][0][cx]);
                    acc[1][1][cx] = f2fma(iB, w01.y, acc[1][1][cx]);
                    acc[2][0][cx] = f2fma(iA, w23.x, acc[2][0][cx]);
                    acc[2][1][cx] = f2fma(iB, w23.x, acc[2][1][cx]);
                    acc[3][0][cx] = f2fma(iA, w23.y, acc[3][0][cx]);
                    acc[3][1][cx] = f2fma(iB, w23.y, acc[3][1][cx]);
                }
            }
        }
    }

    int py = by * 4 + ty, px = bx * 16 + xc;
#pragma unroll
    for (int c = 0; c < 4; c++) {
        int co = cog * 4 + c;
        float bb = s_b[co];
        float a00, b00, a01, b01, a10, b10, a11, b11;
        upk2(acc[c][0][0], a00, b00);
        upk2(acc[c][0][1], a01, b01);
        upk2(acc[c][1][0], a10, b10);
        upk2(acc[c][1][1], a11, b11);
        float m0 = fmaxf(fmaxf(fmaxf(a00, a01), fmaxf(a10, a11)) + bb, 0.f);
        float m1 = fmaxf(fmaxf(fmaxf(b00, b01), fmaxf(b10, b11)) + bb, 0.f);
        g_poolp[((bp * 16 + co) * 256 + py) * 256 + px] = make_float2(m0, m1);
    }
}

// ---------------------------------------------------------------------------
// K2: conv2(16->32)+BN+ReLU, batch-pair packed; feature map never stored.
// Tile 16x8 px. 256 thr = 8 cogs(4ch) x 32 spatial (thread = 4 px).
// MODE 0: pair (0,8), lane0 -> proposal mask + count. MODE 1: masked sums.
// ---------------------------------------------------------------------------
#define K2_IN_OFF     0
#define K2_W_OFF      (16 * 10 * 18 * 8)               // 23040
#define K2_B_OFF      (K2_W_OFF + 144 * 32 * 8)        // 59904
#define K2_PF_OFF     (K2_B_OFF + 128)                 // 60032
#define K2_SC_OFF     (K2_PF_OFF + 128)                // 60160
#define K2_SMEM_TOTAL (K2_SC_OFF + 7 * 128 * 4)        // 63744

template <int MODE>
__global__ __launch_bounds__(256, 3) void k2_kernel(const float* __restrict__ pf_w,
                                                    const float* __restrict__ pf_b) {
    extern __shared__ char smem[];
    float2*             s_in = (float2*)smem;                          // [16][10][18]
    unsigned long long* s_w  = (unsigned long long*)(smem + K2_W_OFF); // [144][32]
    float*              s_b  = (float*)(smem + K2_B_OFF);
    float*              s_pf = (float*)(smem + K2_PF_OFF);
    float*              s_sc = (float*)(smem + K2_SC_OFF);             // [7][128]

    int tid = threadIdx.x;
    int bp = blockIdx.z, bx = blockIdx.x, by = blockIdx.y;

    for (int i = tid; i < 4608; i += 256) s_w[i] = g_w2p[i];
    if (tid < 32) {
        s_b[tid] = g_bias2[tid];
        if (MODE == 0) s_pf[tid] = pf_w[tid];
    }

    int y0 = by * 8 - 1, x0 = bx * 16 - 1;
    const float2* poolb = g_poolp + (size_t)bp * 16 * 65536;
    for (int i = tid; i < 2880; i += 256) {  // 16*10*18
        int cin = i / 180, rem = i % 180, r = rem / 18, c = rem % 18;
        int gy = y0 + r, gx = x0 + c;
        float2 v = make_float2(0.f, 0.f);
        if ((unsigned)gy < 256u && (unsigned)gx < 256u)
            v = poolb[(cin * 256 + gy) * 256 + gx];
        s_in[cin * 180 + r * 18 + c] = v;
    }
    __syncthreads();

    int cog = tid >> 5, sp = tid & 31, ry = sp >> 2, xc = sp & 3;
    unsigned long long acc[4][4];  // [ch][px]
#pragma unroll
    for (int c = 0; c < 4; c++)
#pragma unroll
        for (int p = 0; p < 4; p++) acc[c][p] = 0ull;

    for (int cin = 0; cin < 16; cin++) {
        const unsigned long long* base =
            (const unsigned long long*)(s_in + cin * 180) + 4 * xc;
#pragma unroll
        for (int ky = 0; ky < 3; ky++) {
            const ulonglong2* pr = (const ulonglong2*)(base + (ry + ky) * 18);
            ulonglong2 q0 = pr[0], q1 = pr[1], q2 = pr[2];
            unsigned long long e[6] = {q0.x, q0.y, q1.x, q1.y, q2.x, q2.y};
#pragma unroll
            for (int kx = 0; kx < 3; kx++) {
                const ulonglong2* wv =
                    (const ulonglong2*)(s_w + (cin * 9 + ky * 3 + kx) * 32 + cog * 4);
                ulonglong2 w01 = wv[0], w23 = wv[1];
#pragma unroll
                for (int p = 0; p < 4; p++) {
                    unsigned long long iv = e[kx + p];
                    acc[0][p] = f2fma(iv, w01.x, acc[0][p]);
                    acc[1][p] = f2fma(iv, w01.y, acc[1][p]);
                    acc[2][p] = f2fma(iv, w23.x, acc[2][p]);
                    acc[3][p] = f2fma(iv, w23.y, acc[3][p]);
                }
            }
        }
    }

    int y = by * 8 + ry, xg = bx * 16 + xc * 4;

    if (MODE == 0) {
        float sc[4] = {0.f, 0.f, 0.f, 0.f};
#pragma unroll
        for (int c = 0; c < 4; c++) {
            float bb = s_b[cog * 4 + c], pw = s_pf[cog * 4 + c];
#pragma unroll
            for (int p = 0; p < 4; p++) {
                float v0, v1;
                upk2(acc[c][p], v0, v1);
                sc[p] += fmaxf(v0 + bb, 0.f) * pw;  // lane0 = batch 0
            }
        }
        if (cog > 0) {
            float* d = s_sc + (cog - 1) * 128 + sp * 4;
#pragma unroll
            for (int p = 0; p < 4; p++) d[p] = sc[p];
        }
        __syncthreads();
        if (cog == 0) {
            float pb = pf_b[0];
            uchar4 mv;
            unsigned char* mb = (unsigned char*)&mv;
            int cnt = 0;
#pragma unroll
            for (int p = 0; p < 4; p++) {
                float t = sc[p] + pb;
#pragma unroll
                for (int g = 0; g < 7; g++) t += s_sc[g * 128 + sp * 4 + p];
                mb[p] = t > 0.f;
                cnt += mb[p];
            }
            *(uchar4*)(g_mask + y * 256 + xg) = mv;
            cnt = __reduce_add_sync(0xffffffffu, cnt);
            if (sp == 0) atomicAdd(&g_count_i, cnt);
        }
    } else {
        uchar4 mm = *(const uchar4*)(g_mask + y * 256 + xg);
        float mk[4] = {(float)mm.x, (float)mm.y, (float)mm.z, (float)mm.w};
#pragma unroll
        for (int c = 0; c < 4; c++) {
            float bb = s_b[cog * 4 + c];
            float p0 = 0.f, p1 = 0.f;
#pragma unroll
            for (int p = 0; p < 4; p++) {
                float v0, v1;
                upk2(acc[c][p], v0, v1);
                p0 += mk[p] * fmaxf(v0 + bb, 0.f);
                p1 += mk[p] * fmaxf(v1 + bb, 0.f);
            }
#pragma unroll
            for (int off = 16; off > 0; off >>= 1) {
                p0 += __shfl_xor_sync(0xffffffffu, p0, off);
                p1 += __shfl_xor_sync(0xffffffffu, p1, off);
            }
            if (sp == 0) {
                atomicAdd(&g_S[bp * 32 + cog * 4 + c], p0);
                atomicAdd(&g_S[(bp + 8) * 32 + cog * 4 + c], p1);
            }
        }
    }
}

// ---------------------------------------------------------------------------
__global__ void k3_kernel(const float* __restrict__ vw, const float* __restrict__ vb,
                          const float* __restrict__ cw, const float* __restrict__ cb,
                          float* __restrict__ out) {
    __shared__ float s_mean[512];
    __shared__ float s_cm[1280];
    int t = threadIdx.x;  // 256
    int cnt = g_count_i;
    float denom = (float)(cnt > 0 ? cnt : 1);
    float frac = cnt > 0 ? 1.f : 0.f;
    for (int i = t; i < 512; i += 256) s_mean[i] = g_S[i] / denom;
    __syncthreads();
    for (int i = t; i < 16 * 80; i += 256) {
        int b = i / 80, k = i % 80;
        float a = vb[k] * frac;
        const float* wm = vw + k * 32;
        const float* mm = s_mean + b * 32;
#pragma unroll
        for (int c = 0; c < 32; c++) a += mm[c] * wm[c];
        s_cm[i] = a;
    }
    __syncthreads();
    for (int i = t; i < 1280; i += 256) {
        int b = i / 80, j = i % 80;
        float a = cb[j];
        const float* w = cw + j * 80;
        const float* m = s_cm + b * 80;
#pragma unroll
        for (int k = 0; k < 80; k++) a += m[k] * w[k];
        out[i] = a;
    }
}

// ---------------------------------------------------------------------------
extern "C" void kernel_launch(void* const* d_in, const int* in_sizes, int n_in,
                              void* d_out, int out_size) {
    const float* x   = (const float*)d_in[0];
    const float* w1  = (const float*)d_in[1];
    const float* g1  = (const float*)d_in[2];
    const float* b1  = (const float*)d_in[3];
    const float* m1  = (const float*)d_in[4];
    const float* v1  = (const float*)d_in[5];
    const float* w2  = (const float*)d_in[6];
    const float* g2  = (const float*)d_in[7];
    const float* b2  = (const float*)d_in[8];
    const float* m2  = (const float*)d_in[9];
    const float* v2  = (const float*)d_in[10];
    const float* pfw = (const float*)d_in[11];
    const float* pfb = (const float*)d_in[12];
    const float* vw  = (const float*)d_in[13];
    const float* vb  = (const float*)d_in[14];
    const float* cw  = (const float*)d_in[15];
    const float* cb  = (const float*)d_in[16];
    float* out = (float*)d_out;

    cudaFuncSetAttribute(k2_kernel<0>, cudaFuncAttributeMaxDynamicSharedMemorySize,
                         K2_SMEM_TOTAL);
    cudaFuncSetAttribute(k2_kernel<1>, cudaFuncAttributeMaxDynamicSharedMemorySize,
                         K2_SMEM_TOTAL);

    prep_kernel<<<1, 256>>>(w1, g1, b1, m1, v1, w2, g2, b2, m2, v2);
    k1_kernel<<<dim3(16, 64, 8), 256>>>(x);
    k2_kernel<0><<<dim3(16, 32, 1), 256, K2_SMEM_TOTAL>>>(pfw, pfb);
    k2_kernel<1><<<dim3(16, 32, 8), 256, K2_SMEM_TOTAL>>>(pfw, pfb);
    k3_kernel<<<1, 256>>>(vw, vb, cw, cb, out);
}

// round 6
// speedup vs baseline: 1.9529x; 1.5322x over previous
#include <cuda_runtime.h>
#include <cuda_bf16.h>
#include <cstdint>

#define BN_EPS 1e-5f

// ---------------- device scratch ----------------
__device__ float              g_pcl[16 * 256 * 256 * 16];  // [b][y][x][ci] channels-last
__device__ float              g_wf[9 * 2 * 4 * 2 * 32];    // B fragments, lane-ordered
__device__ unsigned char      g_mask[256 * 256];
__device__ int                g_count_i;
__device__ float              g_S[16 * 32];
__device__ unsigned long long g_w1p[27 * 16];              // conv1 folded, packed {w,w}
__device__ float              g_bias1[16];
__device__ float              g_bias2[32];

// ---- f32x2 helpers (K1 scalar engine) ----
__device__ __forceinline__ unsigned long long pk2(float a, float b) {
    unsigned long long r;
    asm("mov.b64 %0, {%1, %2};" : "=l"(r) : "f"(a), "f"(b));
    return r;
}
__device__ __forceinline__ void upk2(unsigned long long v, float& a, float& b) {
    asm("mov.b64 {%0, %1}, %2;" : "=f"(a), "=f"(b) : "l"(v));
}
__device__ __forceinline__ unsigned long long f2fma(unsigned long long a,
                                                    unsigned long long b,
                                                    unsigned long long c) {
    unsigned long long d;
    asm("fma.rn.f32x2 %0, %1, %2, %3;" : "=l"(d) : "l"(a), "l"(b), "l"(c));
    return d;
}

// ---- tf32 warp MMA (sm_80+ PTX; maps to HMMA on sm_100) ----
__device__ __forceinline__ void mma_tf32(float& d0, float& d1, float& d2, float& d3,
                                         uint32_t a0, uint32_t a1, uint32_t a2,
                                         uint32_t a3, uint32_t b0, uint32_t b1) {
    asm volatile(
        "mma.sync.aligned.m16n8k8.row.col.f32.tf32.tf32.f32 "
        "{%0,%1,%2,%3}, {%4,%5,%6,%7}, {%8,%9}, {%0,%1,%2,%3};"
        : "+f"(d0), "+f"(d1), "+f"(d2), "+f"(d3)
        : "r"(a0), "r"(a1), "r"(a2), "r"(a3), "r"(b0), "r"(b1));
}

// ---------------------------------------------------------------------------
// prep: fold BN into weights; build conv1 packed weights and conv2 B-fragments.
// B-fragment for mma.m16n8k8 (B is K8 x N8, thread lane: g=lane>>2, tg=lane&3):
//   reg0 = B[k=tg][n=g], reg1 = B[k=tg+4][n=g]
// g_wf[((tap*2+ks)*4+nt)*64 + reg*32 + lane], ci = ks*8+k, cout = nt*8+n.
// ---------------------------------------------------------------------------
__global__ void prep_kernel(const float* __restrict__ w1,
                            const float* __restrict__ g1, const float* __restrict__ b1,
                            const float* __restrict__ m1, const float* __restrict__ v1,
                            const float* __restrict__ w2,
                            const float* __restrict__ g2, const float* __restrict__ b2,
                            const float* __restrict__ m2, const float* __restrict__ v2) {
    int t = threadIdx.x;  // 256
    for (int i = t; i < 512; i += 256) g_S[i] = 0.f;
    if (t == 0) g_count_i = 0;
    for (int i = t; i < 16 * 27; i += 256) {
        int co = i / 27, k = i % 27;
        float s = g1[co] * rsqrtf(v1[co] + BN_EPS);
        g_w1p[k * 16 + co] = pk2(w1[co * 27 + k] * s, w1[co * 27 + k] * s);
    }
    for (int i = t; i < 4608; i += 256) {
        int lane = i & 31, reg = (i >> 5) & 1, nt = (i >> 6) & 3;
        int ks = (i >> 8) & 1, tap = i >> 9;
        int g = lane >> 2, tg = lane & 3;
        int ky = tap / 3, kx = tap % 3;
        int ci = ks * 8 + tg + reg * 4;
        int cout = nt * 8 + g;
        float s = g2[cout] * rsqrtf(v2[cout] + BN_EPS);
        g_wf[i] = w2[((cout * 16 + ci) * 3 + ky) * 3 + kx] * s;
    }
    if (t < 16) {
        float s = g1[t] * rsqrtf(v1[t] + BN_EPS);
        g_bias1[t] = b1[t] - m1[t] * s;
    }
    if (t < 32) {
        float s = g2[t] * rsqrtf(v2[t] + BN_EPS);
        g_bias2[t] = b2[t] - m2[t] * s;
    }
}

// ---------------------------------------------------------------------------
// K1: conv1+bn+relu+maxpool (scalar f32x2, batch pair in lanes), channels-last
// output via smem staging. Conv tile 32x8 (pooled 16x4).
// ---------------------------------------------------------------------------
__global__ __launch_bounds__(256, 3) void k1_kernel(const float* __restrict__ x) {
    __shared__ float2             s_x[3 * 10 * 34];
    __shared__ unsigned long long s_w[27 * 16];
    __shared__ float              s_b[16];
    __shared__ float              s_out[2 * 4 * 16 * 16];  // [bh][ty][xc][ci]

    int bp = blockIdx.z, bx = blockIdx.x, by = blockIdx.y;
    int tid = threadIdx.x;

    for (int i = tid; i < 27 * 16; i += 256) s_w[i] = g_w1p[i];
    if (tid < 16) s_b[tid] = g_bias1[tid];

    int y0 = by * 8 - 1, x0 = bx * 32 - 1;
    const float* xa = x + (size_t)bp * 3 * 512 * 512;
    const float* xb = x + (size_t)(bp + 8) * 3 * 512 * 512;
    for (int i = tid; i < 3 * 10 * 34; i += 256) {
        int cin = i / 340, rem = i % 340, r = rem / 34, c = rem % 34;
        int gy = y0 + r, gx = x0 + c;
        float a = 0.f, b = 0.f;
        if ((unsigned)gy < 512u && (unsigned)gx < 512u) {
            size_t off = ((size_t)cin * 512 + gy) * 512 + gx;
            a = xa[off];
            b = xb[off];
        }
        s_x[cin * 340 + r * 34 + c] = make_float2(a, b);
    }
    __syncthreads();

    int cog = tid >> 6, sp = tid & 63, ty = sp >> 4, xc = sp & 15;
    unsigned long long acc[4][2][2];
#pragma unroll
    for (int c = 0; c < 4; c++)
#pragma unroll
        for (int r = 0; r < 2; r++) { acc[c][r][0] = 0ull; acc[c][r][1] = 0ull; }

#pragma unroll
    for (int cin = 0; cin < 3; cin++) {
        const unsigned long long* base =
            (const unsigned long long*)(s_x + cin * 340) + 2 * xc;
#pragma unroll
        for (int ky = 0; ky < 3; ky++) {
            const ulonglong2* pA = (const ulonglong2*)(base + (2 * ty + ky) * 34);
            const ulonglong2* pB = (const ulonglong2*)(base + (2 * ty + ky + 1) * 34);
            ulonglong2 qa0 = pA[0], qa1 = pA[1];
            ulonglong2 qb0 = pB[0], qb1 = pB[1];
            unsigned long long rA[4] = {qa0.x, qa0.y, qa1.x, qa1.y};
            unsigned long long rB[4] = {qb0.x, qb0.y, qb1.x, qb1.y};
#pragma unroll
            for (int kx = 0; kx < 3; kx++) {
                const ulonglong2* wv =
                    (const ulonglong2*)(s_w + (cin * 9 + ky * 3 + kx) * 16 + cog * 4);
                ulonglong2 w01 = wv[0], w23 = wv[1];
#pragma unroll
                for (int cx = 0; cx < 2; cx++) {
                    unsigned long long iA = rA[kx + cx];
                    unsigned long long iB = rB[kx + cx];
                    acc[0][0][cx] = f2fma(iA, w01.x, acc[0][0][cx]);
                    acc[0][1][cx] = f2fma(iB, w01.x, acc[0][1][cx]);
                    acc[1][0][cx] = f2fma(iA, w01.y, acc[1][0][cx]);
                    acc[1][1][cx] = f2fma(iB, w01.y, acc[1][1][cx]);
                    acc[2][0][cx] = f2fma(iA, w23.x, acc[2][0][cx]);
                    acc[2][1][cx] = f2fma(iB, w23.x, acc[2][1][cx]);
                    acc[3][0][cx] = f2fma(iA, w23.y, acc[3][0][cx]);
                    acc[3][1][cx] = f2fma(iB, w23.y, acc[3][1][cx]);
                }
            }
        }
    }

#pragma unroll
    for (int c = 0; c < 4; c++) {
        int co = cog * 4 + c;
        float bb = s_b[co];
        float a00, b00, a01, b01, a10, b10, a11, b11;
        upk2(acc[c][0][0], a00, b00);
        upk2(acc[c][0][1], a01, b01);
        upk2(acc[c][1][0], a10, b10);
        upk2(acc[c][1][1], a11, b11);
        float m0 = fmaxf(fmaxf(fmaxf(a00, a01), fmaxf(a10, a11)) + bb, 0.f);
        float m1 = fmaxf(fmaxf(fmaxf(b00, b01), fmaxf(b10, b11)) + bb, 0.f);
        s_out[((0 * 4 + ty) * 16 + xc) * 16 + co] = m0;
        s_out[((1 * 4 + ty) * 16 + xc) * 16 + co] = m1;
    }
    __syncthreads();

    const float4* so = (const float4*)s_out;
#pragma unroll
    for (int k = 0; k < 2; k++) {
        int idx = tid + k * 256;
        int ci4 = idx & 3, xcc = (idx >> 2) & 15, tyy = (idx >> 6) & 3, bh = idx >> 8;
        int b = bp + bh * 8;
        int py = by * 4 + tyy, px = bx * 16 + xcc;
        *(float4*)(g_pcl + (((size_t)(b * 256 + py) * 256 + px) * 16) + ci4 * 4) = so[idx];
    }
}

// ---------------------------------------------------------------------------
// K2: conv2 via warp-level tf32 mma. CTA = 1 row x 128 px, 8 warps x 16 px.
// A smem: 3 rows x 130 px x 16 ch, pitch 20 floats (conflict-free fragments).
// MODE 0: batch 0 -> mask + count.  MODE 1: masked channel sums.
// ---------------------------------------------------------------------------
#define SA_FLOATS   (3 * 130 * 20)            // 7800
#define SWF_OFF     SA_FLOATS                 // floats
#define SBIAS_OFF   (SWF_OFF + 4608)          // 12408
#define SPF_OFF     (SBIAS_OFF + 32)          // 12440
#define SRED_OFF    (SPF_OFF + 32)            // 12472
#define K2M_FLOATS  (SRED_OFF + 256)          // 12728
#define K2M_SMEM    (K2M_FLOATS * 4)          // 50912 B

template <int MODE>
__global__ __launch_bounds__(256) void k2m_kernel(const float* __restrict__ pf_w,
                                                  const float* __restrict__ pf_b) {
    extern __shared__ float sm[];
    float* s_A    = sm;
    float* s_wf   = sm + SWF_OFF;
    float* s_bias = sm + SBIAS_OFF;
    float* s_pf   = sm + SPF_OFF;
    float* s_red  = sm + SRED_OFF;

    int tid = threadIdx.x;
    int c0 = blockIdx.x * 128, y = blockIdx.y;
    int b = (MODE == 0) ? 0 : blockIdx.z;

    for (int i = tid; i < 1152; i += 256)
        ((float4*)s_wf)[i] = ((const float4*)g_wf)[i];
    if (tid < 32) {
        s_bias[tid] = g_bias2[tid];
        s_pf[tid] = pf_w[tid];
    }

    // A tile fill: 3 rows x 130 px, 16 ch each, pitch 20
    for (int cell = tid; cell < 390; cell += 256) {
        int j = cell / 130, i = cell % 130;
        int yy = y + j - 1, px = c0 + i - 1;
        float4 v0 = {0, 0, 0, 0}, v1 = v0, v2 = v0, v3 = v0;
        if ((unsigned)yy < 256u && (unsigned)px < 256u) {
            const float4* src =
                (const float4*)(g_pcl + ((size_t)(b * 256 + yy) * 256 + px) * 16);
            v0 = src[0]; v1 = src[1]; v2 = src[2]; v3 = src[3];
        }
        float4* d = (float4*)(s_A + (size_t)cell * 20);
        d[0] = v0; d[1] = v1; d[2] = v2; d[3] = v3;
    }
    __syncthreads();

    int w = tid >> 5, lane = tid & 31;
    int g = lane >> 2, tg = lane & 3;

    float d[4][4];
#pragma unroll
    for (int nt = 0; nt < 4; nt++)
#pragma unroll
        for (int i = 0; i < 4; i++) d[nt][i] = 0.f;

#pragma unroll
    for (int ky = 0; ky < 3; ky++) {
#pragma unroll
        for (int kx = 0; kx < 3; kx++) {
            int tap = ky * 3 + kx;
            const float* ar0 = s_A + (ky * 130 + 16 * w + g + kx) * 20;
            const float* ar1 = ar0 + 160;
#pragma unroll
            for (int ks = 0; ks < 2; ks++) {
                uint32_t a0 = __float_as_uint(ar0[ks * 8 + tg]);
                uint32_t a1 = __float_as_uint(ar1[ks * 8 + tg]);
                uint32_t a2 = __float_as_uint(ar0[ks * 8 + tg + 4]);
                uint32_t a3 = __float_as_uint(ar1[ks * 8 + tg + 4]);
                const float* bf = s_wf + (tap * 2 + ks) * 256;
#pragma unroll
                for (int nt = 0; nt < 4; nt++) {
                    uint32_t b0 = __float_as_uint(bf[nt * 64 + lane]);
                    uint32_t b1 = __float_as_uint(bf[nt * 64 + 32 + lane]);
                    mma_tf32(d[nt][0], d[nt][1], d[nt][2], d[nt][3],
                             a0, a1, a2, a3, b0, b1);
                }
            }
        }
    }

    // D mapping: rows = px (16w+g, 16w+g+8), cols = cout (nt*8+2tg, +1)
    if (MODE == 0) {
        float s0 = 0.f, s1 = 0.f;
#pragma unroll
        for (int nt = 0; nt < 4; nt++) {
            float b0n = s_bias[nt * 8 + 2 * tg], b1n = s_bias[nt * 8 + 2 * tg + 1];
            float p0n = s_pf[nt * 8 + 2 * tg], p1n = s_pf[nt * 8 + 2 * tg + 1];
            s0 += fmaxf(d[nt][0] + b0n, 0.f) * p0n + fmaxf(d[nt][1] + b1n, 0.f) * p1n;
            s1 += fmaxf(d[nt][2] + b0n, 0.f) * p0n + fmaxf(d[nt][3] + b1n, 0.f) * p1n;
        }
        s0 += __shfl_xor_sync(0xffffffffu, s0, 1);
        s0 += __shfl_xor_sync(0xffffffffu, s0, 2);
        s1 += __shfl_xor_sync(0xffffffffu, s1, 1);
        s1 += __shfl_xor_sync(0xffffffffu, s1, 2);
        int cnt = 0;
        if (tg == 0) {
            float pb = pf_b[0];
            int px = c0 + 16 * w + g;
            unsigned char m0 = (s0 + pb) > 0.f;
            unsigned char m1 = (s1 + pb) > 0.f;
            g_mask[y * 256 + px] = m0;
            g_mask[y * 256 + px + 8] = m1;
            cnt = m0 + m1;
        }
        cnt = __reduce_add_sync(0xffffffffu, cnt);
        if (lane == 0) atomicAdd(&g_count_i, cnt);
    } else {
        int px = c0 + 16 * w + g;
        float mg = (float)g_mask[y * 256 + px];
        float mg8 = (float)g_mask[y * 256 + px + 8];
        float a0v[4], a1v[4];
#pragma unroll
        for (int nt = 0; nt < 4; nt++) {
            float b0n = s_bias[nt * 8 + 2 * tg], b1n = s_bias[nt * 8 + 2 * tg + 1];
            a0v[nt] = mg * fmaxf(d[nt][0] + b0n, 0.f) + mg8 * fmaxf(d[nt][2] + b0n, 0.f);
            a1v[nt] = mg * fmaxf(d[nt][1] + b1n, 0.f) + mg8 * fmaxf(d[nt][3] + b1n, 0.f);
        }
#pragma unroll
        for (int nt = 0; nt < 4; nt++) {
#pragma unroll
            for (int off = 4; off <= 16; off <<= 1) {
                a0v[nt] += __shfl_xor_sync(0xffffffffu, a0v[nt], off);
                a1v[nt] += __shfl_xor_sync(0xffffffffu, a1v[nt], off);
            }
        }
        if (g == 0) {
#pragma unroll
            for (int nt = 0; nt < 4; nt++) {
                s_red[w * 32 + nt * 8 + 2 * tg] = a0v[nt];
                s_red[w * 32 + nt * 8 + 2 * tg + 1] = a1v[nt];
            }
        }
        __syncthreads();
        if (tid < 32) {
            float s = 0.f;
#pragma unroll
            for (int ww = 0; ww < 8; ww++) s += s_red[ww * 32 + tid];
            atomicAdd(&g_S[b * 32 + tid], s);
        }
    }
}

// ---------------------------------------------------------------------------
__global__ void k3_kernel(const float* __restrict__ vw, const float* __restrict__ vb,
                          const float* __restrict__ cw, const float* __restrict__ cb,
                          float* __restrict__ out) {
    __shared__ float s_mean[512];
    __shared__ float s_cm[1280];
    int t = threadIdx.x;  // 256
    int cnt = g_count_i;
    float denom = (float)(cnt > 0 ? cnt : 1);
    float frac = cnt > 0 ? 1.f : 0.f;
    for (int i = t; i < 512; i += 256) s_mean[i] = g_S[i] / denom;
    __syncthreads();
    for (int i = t; i < 16 * 80; i += 256) {
        int b = i / 80, k = i % 80;
        float a = vb[k] * frac;
        const float* wm = vw + k * 32;
        const float* mm = s_mean + b * 32;
#pragma unroll
        for (int c = 0; c < 32; c++) a += mm[c] * wm[c];
        s_cm[i] = a;
    }
    __syncthreads();
    for (int i = t; i < 1280; i += 256) {
        int b = i / 80, j = i % 80;
        float a = cb[j];
        const float* w = cw + j * 80;
        const float* m = s_cm + b * 80;
#pragma unroll
        for (int k = 0; k < 80; k++) a += m[k] * w[k];
        out[i] = a;
    }
}

// ---------------------------------------------------------------------------
extern "C" void kernel_launch(void* const* d_in, const int* in_sizes, int n_in,
                              void* d_out, int out_size) {
    const float* x   = (const float*)d_in[0];
    const float* w1  = (const float*)d_in[1];
    const float* g1  = (const float*)d_in[2];
    const float* b1  = (const float*)d_in[3];
    const float* m1  = (const float*)d_in[4];
    const float* v1  = (const float*)d_in[5];
    const float* w2  = (const float*)d_in[6];
    const float* g2  = (const float*)d_in[7];
    const float* b2  = (const float*)d_in[8];
    const float* m2  = (const float*)d_in[9];
    const float* v2  = (const float*)d_in[10];
    const float* pfw = (const float*)d_in[11];
    const float* pfb = (const float*)d_in[12];
    const float* vw  = (const float*)d_in[13];
    const float* vb  = (const float*)d_in[14];
    const float* cw  = (const float*)d_in[15];
    const float* cb  = (const float*)d_in[16];
    float* out = (float*)d_out;

    cudaFuncSetAttribute(k2m_kernel<0>, cudaFuncAttributeMaxDynamicSharedMemorySize,
                         K2M_SMEM);
    cudaFuncSetAttribute(k2m_kernel<1>, cudaFuncAttributeMaxDynamicSharedMemorySize,
                         K2M_SMEM);

    prep_kernel<<<1, 256>>>(w1, g1, b1, m1, v1, w2, g2, b2, m2, v2);
    k1_kernel<<<dim3(16, 64, 8), 256>>>(x);
    k2m_kernel<0><<<dim3(2, 256, 1), 256, K2M_SMEM>>>(pfw, pfb);
    k2m_kernel<1><<<dim3(2, 256, 16), 256, K2M_SMEM>>>(pfw, pfb);
    k3_kernel<<<1, 256>>>(vw, vb, cw, cb, out);
}

// round 7
// speedup vs baseline: 2.0994x; 1.0750x over previous
#include <cuda_runtime.h>
#include <cstdint>

#define BN_EPS 1e-5f

// ---------------- device scratch ----------------
// g_pcl stores channels PERMUTED: slot s holds channel ci = (s>>2) + 4*(s&3)
// (4x4 transpose, self-inverse) so K2's per-thread A-regs are one float4.
__device__ float         g_pcl[16 * 256 * 256 * 16];
__device__ float4        g_wf4[36 * 32];   // conv2 B fragments: [tap][nt][lane]
__device__ float4        g_w1f4[6 * 32];   // conv1 B fragments: [ky][nt][lane]
__device__ unsigned char g_mask[256 * 256];
__device__ int           g_count_i;
__device__ float         g_S[16 * 32];
__device__ float         g_bias1[16];
__device__ float         g_bias2[32];

// ---------------- helpers ----------------
__device__ __forceinline__ float rna(float x) {  // round fp32 -> tf32 (RN)
    uint32_t r;
    asm("cvt.rna.tf32.f32 %0, %1;" : "=r"(r) : "f"(x));
    return __uint_as_float(r);
}
__device__ __forceinline__ void mma8(float* d, uint32_t a0, uint32_t a1, uint32_t a2,
                                     uint32_t a3, uint32_t b0, uint32_t b1) {
    asm volatile(
        "mma.sync.aligned.m16n8k8.row.col.f32.tf32.tf32.f32 "
        "{%0,%1,%2,%3},{%4,%5,%6,%7},{%8,%9},{%0,%1,%2,%3};"
        : "+f"(d[0]), "+f"(d[1]), "+f"(d[2]), "+f"(d[3])
        : "r"(a0), "r"(a1), "r"(a2), "r"(a3), "r"(b0), "r"(b1));
}
__device__ __forceinline__ void mma4(float* d, uint32_t a0, uint32_t a1, uint32_t b0) {
    asm volatile(
        "mma.sync.aligned.m16n8k4.row.col.f32.tf32.tf32.f32 "
        "{%0,%1,%2,%3},{%4,%5},{%6},{%0,%1,%2,%3};"
        : "+f"(d[0]), "+f"(d[1]), "+f"(d[2]), "+f"(d[3])
        : "r"(a0), "r"(a1), "r"(b0));
}

// ---------------------------------------------------------------------------
// prep: fold BN, build rounded tf32 weight fragments for both convs.
// conv2 fragment float4 per (tap,nt,lane): {ks0.b0, ks0.b1, ks1.b0, ks1.b1},
//   b(ks,reg) = w2f[cout=nt*8+g][ci=ks*8+tg+4*reg][ky][kx]
// conv1 fragment float4 per (ky,nt,lane): {dx0, dx1, dx2, 0},
//   dx-reg r = w1f[cout=nt*8+g][ci=tg (<3)][ky][kx=r]
// ---------------------------------------------------------------------------
__global__ void prep_kernel(const float* __restrict__ w1,
                            const float* __restrict__ g1, const float* __restrict__ b1,
                            const float* __restrict__ m1, const float* __restrict__ v1,
                            const float* __restrict__ w2,
                            const float* __restrict__ g2, const float* __restrict__ b2,
                            const float* __restrict__ m2, const float* __restrict__ v2) {
    int t = threadIdx.x;  // 256
    for (int i = t; i < 512; i += 256) g_S[i] = 0.f;
    if (t == 0) g_count_i = 0;

    if (t < 192) {  // conv1 fragments
        int lane = t & 31, nt = (t >> 5) & 1, ky = t >> 6;
        int g = lane >> 2, tg = lane & 3;
        int n = nt * 8 + g;
        float s = g1[n] * rsqrtf(v1[n] + BN_EPS);
        float r[3];
#pragma unroll
        for (int dx = 0; dx < 3; dx++)
            r[dx] = (tg < 3) ? rna(w1[((n * 3 + tg) * 3 + ky) * 3 + dx] * s) : 0.f;
        g_w1f4[t] = make_float4(r[0], r[1], r[2], 0.f);
    }
    for (int i = t; i < 1152; i += 256) {  // conv2 fragments
        int lane = i & 31, nt = (i >> 5) & 3, tap = i >> 7;
        int g = lane >> 2, tg = lane & 3;
        int ky = tap / 3, kx = tap % 3;
        int n = nt * 8 + g;
        float s = g2[n] * rsqrtf(v2[n] + BN_EPS);
        float4 f;
        f.x = rna(w2[((n * 16 + (tg + 0)) * 3 + ky) * 3 + kx] * s);
        f.y = rna(w2[((n * 16 + (tg + 4)) * 3 + ky) * 3 + kx] * s);
        f.z = rna(w2[((n * 16 + (tg + 8)) * 3 + ky) * 3 + kx] * s);
        f.w = rna(w2[((n * 16 + (tg + 12)) * 3 + ky) * 3 + kx] * s);
        g_wf4[i] = f;
    }
    if (t < 16) {
        float s = g1[t] * rsqrtf(v1[t] + BN_EPS);
        g_bias1[t] = b1[t] - m1[t] * s;
    }
    if (t < 32) {
        float s = g2[t] * rsqrtf(v2[t] + BN_EPS);
        g_bias2[t] = b2[t] - m2[t] * s;
    }
}

// ---------------------------------------------------------------------------
// K1: conv1(3->16)+bn+relu+maxpool via tf32 mma.
// CTA = 128 conv px x 4 conv rows (= 64 x 2 pooled). 8 warps x 16 px.
// Input tile channels-last [row][px][4ci] pitch 4; per ky: one k8 + one k4 MMA.
// A cached in 36 regs. Pool: register row-max + shfl_xor(4) px-pair max.
// ---------------------------------------------------------------------------
__global__ __launch_bounds__(256) void k1t_kernel(const float* __restrict__ x) {
    __shared__ float  s_a[6 * 132 * 4];     // [row][pxcell][ci]
    __shared__ float4 s_wf[192];
    __shared__ float  s_b[16];
    __shared__ float  s_out[2 * 64 * 16];   // [q][ppx][slot]

    int b = blockIdx.z, bx = blockIdx.x, by = blockIdx.y;
    int tid = threadIdx.x;

    if (tid < 192) s_wf[tid] = g_w1f4[tid];
    if (tid < 16) s_b[tid] = g_bias1[tid];
    for (int i = tid; i < 6 * 132; i += 256)
        ((float4*)s_a)[i] = make_float4(0.f, 0.f, 0.f, 0.f);
    __syncthreads();

    int y0 = by * 4, x0 = bx * 128;
    for (int i = tid; i < 2340; i += 256) {  // 3ci x 6rows x 130px
        int ci = i / 780, rem = i % 780, r = rem / 130, c = rem % 130;
        int gy = y0 - 1 + r, gx = x0 - 1 + c;
        if ((unsigned)gy < 512u && (unsigned)gx < 512u)
            s_a[(r * 132 + c) * 4 + ci] = rna(x[((b * 3 + ci) * 512 + gy) * 512 + gx]);
    }
    __syncthreads();

    int w = tid >> 5, lane = tid & 31, g = lane >> 2, tg = lane & 3;
    int cb = w * 16 + g;

    uint32_t A[6][3][2];  // [row][dx][half]
#pragma unroll
    for (int rr = 0; rr < 6; rr++)
#pragma unroll
        for (int dx = 0; dx < 3; dx++) {
            A[rr][dx][0] = __float_as_uint(s_a[(rr * 132 + cb + dx) * 4 + tg]);
            A[rr][dx][1] = __float_as_uint(s_a[(rr * 132 + cb + dx + 8) * 4 + tg]);
        }

    float d[4][2][4];
#pragma unroll
    for (int r = 0; r < 4; r++)
#pragma unroll
        for (int nt = 0; nt < 2; nt++)
#pragma unroll
            for (int j = 0; j < 4; j++) d[r][nt][j] = 0.f;

#pragma unroll
    for (int ky = 0; ky < 3; ky++)
#pragma unroll
        for (int nt = 0; nt < 2; nt++) {
            float4 wv = s_wf[(ky * 2 + nt) * 32 + lane];
            uint32_t b0 = __float_as_uint(wv.x);
            uint32_t b1 = __float_as_uint(wv.y);
            uint32_t b2 = __float_as_uint(wv.z);
#pragma unroll
            for (int r = 0; r < 4; r++) {
                int ri = r + ky;
                mma8(d[r][nt], A[ri][0][0], A[ri][0][1], A[ri][1][0], A[ri][1][1], b0, b1);
                mma4(d[r][nt], A[ri][2][0], A[ri][2][1], b2);
            }
        }

    // maxpool 2x2 + bias + relu + tf32-round, stage channels-permuted
#pragma unroll
    for (int q = 0; q < 2; q++)
#pragma unroll
        for (int nt = 0; nt < 2; nt++) {
            float m[4];
#pragma unroll
            for (int j = 0; j < 4; j++) {
                float mm = fmaxf(d[2 * q][nt][j], d[2 * q + 1][nt][j]);
                mm = fmaxf(mm, __shfl_xor_sync(0xffffffffu, mm, 4));
                m[j] = mm;
            }
            if (!(g & 1)) {
                int j = g >> 1;
                int co0 = nt * 8 + 2 * tg, co1 = co0 + 1;
                int sl0 = (co0 & 3) * 4 + (co0 >> 2);
                int sl1 = (co1 & 3) * 4 + (co1 >> 2);
                int base0 = (q * 64 + w * 8 + j) * 16;
                int base1 = (q * 64 + w * 8 + j + 4) * 16;
                s_out[base0 + sl0] = rna(fmaxf(m[0] + s_b[co0], 0.f));
                s_out[base0 + sl1] = rna(fmaxf(m[1] + s_b[co1], 0.f));
                s_out[base1 + sl0] = rna(fmaxf(m[2] + s_b[co0], 0.f));
                s_out[base1 + sl1] = rna(fmaxf(m[3] + s_b[co1], 0.f));
            }
        }
    __syncthreads();

    for (int idx = tid; idx < 512; idx += 256) {
        int q = idx >> 8, rem = idx & 255, ppx = rem >> 2, s4 = rem & 3;
        int py = by * 2 + q, pxg = bx * 64 + ppx;
        ((float4*)(g_pcl + ((size_t)(b * 256 + py) * 256 + pxg) * 16))[s4] =
            ((const float4*)s_out)[idx];
    }
}

// ---------------------------------------------------------------------------
// K2: conv2(16->32)+bn+relu via tf32 mma. CTA = full row (256 px), 8 warps
// x 32 px (2 m-tiles). A: 3 rows x 258 cells x 16 floats, pitch 16
// (conflict-free float4 fragment loads thanks to channel permutation).
// MODE 0: batch 0 -> mask + count.  MODE 1: masked channel sums.
// ---------------------------------------------------------------------------
#define K2_SA_F   (3 * 258 * 16)          // 12384 floats
#define K2_WF_F   K2_SA_F                 // float4 area (byte 49536, 16B aligned)
#define K2_BIAS_F (K2_SA_F + 4608)        // 16992
#define K2_PF_F   (K2_BIAS_F + 32)
#define K2_RED_F  (K2_PF_F + 32)
#define K2_TOT_F  (K2_RED_F + 256)        // 17312
#define K2_SMEM   (K2_TOT_F * 4)          // 69248 B

template <int MODE>
__global__ __launch_bounds__(256) void k2_kernel(const float* __restrict__ pf_w,
                                                 const float* __restrict__ pf_b) {
    extern __shared__ float sm[];
    float*  s_A    = sm;
    float4* s_wf   = (float4*)(sm + K2_WF_F);
    float*  s_bias = sm + K2_BIAS_F;
    float*  s_pf   = sm + K2_PF_F;
    float*  s_red  = sm + K2_RED_F;

    int tid = threadIdx.x;
    int y = blockIdx.x;
    int b = (MODE == 0) ? 0 : blockIdx.y;

    for (int i = tid; i < 1152; i += 256) s_wf[i] = g_wf4[i];
    if (tid < 32) {
        s_bias[tid] = g_bias2[tid];
        s_pf[tid] = pf_w[tid];
    }

    // A fill: rows y-1..y+1, cells 0..257 (px = cell-1), flat float4 copy
    for (int i = tid; i < 3096; i += 256) {
        int row = i / 1032, rem = i % 1032, cell = rem >> 2, j = rem & 3;
        int yy = y - 1 + row;
        float4 v = make_float4(0.f, 0.f, 0.f, 0.f);
        if ((unsigned)yy < 256u && cell >= 1 && cell <= 256)
            v = ((const float4*)(g_pcl +
                                 ((size_t)(b * 256 + yy) * 256 + (cell - 1)) * 16))[j];
        ((float4*)s_A)[i] = v;
    }
    __syncthreads();

    int w = tid >> 5, lane = tid & 31, g = lane >> 2, tg = lane & 3;
    int pxb = w * 32;

    float d[2][4][4];
#pragma unroll
    for (int mt = 0; mt < 2; mt++)
#pragma unroll
        for (int nt = 0; nt < 4; nt++)
#pragma unroll
            for (int j = 0; j < 4; j++) d[mt][nt][j] = 0.f;

#pragma unroll
    for (int ky = 0; ky < 3; ky++)
#pragma unroll
        for (int kx = 0; kx < 3; kx++) {
            int tap = ky * 3 + kx;
            float4 av0[2], av1[2];
#pragma unroll
            for (int mt = 0; mt < 2; mt++) {
                int cell = pxb + mt * 16 + g + kx;
                av0[mt] = ((const float4*)(s_A + (ky * 258 + cell) * 16))[tg];
                av1[mt] = ((const float4*)(s_A + (ky * 258 + cell + 8) * 16))[tg];
            }
#pragma unroll
            for (int nt = 0; nt < 4; nt++) {
                float4 bv = s_wf[(tap * 4 + nt) * 32 + lane];
                uint32_t b00 = __float_as_uint(bv.x), b01 = __float_as_uint(bv.y);
                uint32_t b10 = __float_as_uint(bv.z), b11 = __float_as_uint(bv.w);
#pragma unroll
                for (int mt = 0; mt < 2; mt++) {
                    mma8(d[mt][nt], __float_as_uint(av0[mt].x), __float_as_uint(av1[mt].x),
                         __float_as_uint(av0[mt].y), __float_as_uint(av1[mt].y), b00, b01);
                    mma8(d[mt][nt], __float_as_uint(av0[mt].z), __float_as_uint(av1[mt].z),
                         __float_as_uint(av0[mt].w), __float_as_uint(av1[mt].w), b10, b11);
                }
            }
        }

    if (MODE == 0) {
        float s[2][2] = {{0.f, 0.f}, {0.f, 0.f}};  // [mt][row-half]
#pragma unroll
        for (int mt = 0; mt < 2; mt++)
#pragma unroll
            for (int nt = 0; nt < 4; nt++) {
                float b0n = s_bias[nt * 8 + 2 * tg], b1n = s_bias[nt * 8 + 2 * tg + 1];
                float p0n = s_pf[nt * 8 + 2 * tg], p1n = s_pf[nt * 8 + 2 * tg + 1];
                s[mt][0] += fmaxf(d[mt][nt][0] + b0n, 0.f) * p0n +
                            fmaxf(d[mt][nt][1] + b1n, 0.f) * p1n;
                s[mt][1] += fmaxf(d[mt][nt][2] + b0n, 0.f) * p0n +
                            fmaxf(d[mt][nt][3] + b1n, 0.f) * p1n;
            }
#pragma unroll
        for (int mt = 0; mt < 2; mt++)
#pragma unroll
            for (int h = 0; h < 2; h++) {
                s[mt][h] += __shfl_xor_sync(0xffffffffu, s[mt][h], 1);
                s[mt][h] += __shfl_xor_sync(0xffffffffu, s[mt][h], 2);
            }
        int cnt = 0;
        if (tg == 0) {
            float pb = pf_b[0];
#pragma unroll
            for (int mt = 0; mt < 2; mt++) {
                int px = pxb + mt * 16 + g;
                unsigned char m0 = (s[mt][0] + pb) > 0.f;
                unsigned char m1 = (s[mt][1] + pb) > 0.f;
                g_mask[y * 256 + px] = m0;
                g_mask[y * 256 + px + 8] = m1;
                cnt += m0 + m1;
            }
        }
        cnt = __reduce_add_sync(0xffffffffu, cnt);
        if (lane == 0) atomicAdd(&g_count_i, cnt);
    } else {
        float part[4][2];
#pragma unroll
        for (int nt = 0; nt < 4; nt++) { part[nt][0] = 0.f; part[nt][1] = 0.f; }
#pragma unroll
        for (int mt = 0; mt < 2; mt++) {
            float mA = (float)g_mask[y * 256 + pxb + mt * 16 + g];
            float mB = (float)g_mask[y * 256 + pxb + mt * 16 + g + 8];
#pragma unroll
            for (int nt = 0; nt < 4; nt++) {
                float b0n = s_bias[nt * 8 + 2 * tg], b1n = s_bias[nt * 8 + 2 * tg + 1];
                part[nt][0] += mA * fmaxf(d[mt][nt][0] + b0n, 0.f) +
                               mB * fmaxf(d[mt][nt][2] + b0n, 0.f);
                part[nt][1] += mA * fmaxf(d[mt][nt][1] + b1n, 0.f) +
                               mB * fmaxf(d[mt][nt][3] + b1n, 0.f);
            }
        }
#pragma unroll
        for (int nt = 0; nt < 4; nt++)
#pragma unroll
            for (int h = 0; h < 2; h++) {
#pragma unroll
                for (int off = 4; off <= 16; off <<= 1)
                    part[nt][h] += __shfl_xor_sync(0xffffffffu, part[nt][h], off);
            }
        if (g == 0) {
#pragma unroll
            for (int nt = 0; nt < 4; nt++) {
                s_red[w * 32 + nt * 8 + 2 * tg] = part[nt][0];
                s_red[w * 32 + nt * 8 + 2 * tg + 1] = part[nt][1];
            }
        }
        __syncthreads();
        if (tid < 32) {
            float s = 0.f;
#pragma unroll
            for (int ww = 0; ww < 8; ww++) s += s_red[ww * 32 + tid];
            atomicAdd(&g_S[b * 32 + tid], s);
        }
    }
}

// ---------------------------------------------------------------------------
__global__ void k3_kernel(const float* __restrict__ vw, const float* __restrict__ vb,
                          const float* __restrict__ cw, const float* __restrict__ cb,
                          float* __restrict__ out) {
    __shared__ float s_mean[512];
    __shared__ float s_cm[1280];
    int t = threadIdx.x;  // 256
    int cnt = g_count_i;
    float denom = (float)(cnt > 0 ? cnt : 1);
    float frac = cnt > 0 ? 1.f : 0.f;
    for (int i = t; i < 512; i += 256) s_mean[i] = g_S[i] / denom;
    __syncthreads();
    for (int i = t; i < 16 * 80; i += 256) {
        int b = i / 80, k = i % 80;
        float a = vb[k] * frac;
        const float* wm = vw + k * 32;
        const float* mm = s_mean + b * 32;
#pragma unroll
        for (int c = 0; c < 32; c++) a += mm[c] * wm[c];
        s_cm[i] = a;
    }
    __syncthreads();
    for (int i = t; i < 1280; i += 256) {
        int b = i / 80, j = i % 80;
        float a = cb[j];
        const float* w = cw + j * 80;
        const float* m = s_cm + b * 80;
#pragma unroll
        for (int k = 0; k < 80; k++) a += m[k] * w[k];
        out[i] = a;
    }
}

// ---------------------------------------------------------------------------
extern "C" void kernel_launch(void* const* d_in, const int* in_sizes, int n_in,
                              void* d_out, int out_size) {
    const float* x   = (const float*)d_in[0];
    const float* w1  = (const float*)d_in[1];
    const float* g1  = (const float*)d_in[2];
    const float* b1  = (const float*)d_in[3];
    const float* m1  = (const float*)d_in[4];
    const float* v1  = (const float*)d_in[5];
    const float* w2  = (const float*)d_in[6];
    const float* g2  = (const float*)d_in[7];
    const float* b2  = (const float*)d_in[8];
    const float* m2  = (const float*)d_in[9];
    const float* v2  = (const float*)d_in[10];
    const float* pfw = (const float*)d_in[11];
    const float* pfb = (const float*)d_in[12];
    const float* vw  = (const float*)d_in[13];
    const float* vb  = (const float*)d_in[14];
    const float* cw  = (const float*)d_in[15];
    const float* cb  = (const float*)d_in[16];
    float* out = (float*)d_out;

    cudaFuncSetAttribute(k2_kernel<0>, cudaFuncAttributeMaxDynamicSharedMemorySize,
                         K2_SMEM);
    cudaFuncSetAttribute(k2_kernel<1>, cudaFuncAttributeMaxDynamicSharedMemorySize,
                         K2_SMEM);

    prep_kernel<<<1, 256>>>(w1, g1, b1, m1, v1, w2, g2, b2, m2, v2);
    k1t_kernel<<<dim3(4, 128, 16), 256>>>(x);
    k2_kernel<0><<<dim3(256, 1, 1), 256, K2_SMEM>>>(pfw, pfb);
    k2_kernel<1><<<dim3(256, 16, 1), 256, K2_SMEM>>>(pfw, pfb);
    k3_kernel<<<1, 256>>>(vw, vb, cw, cb, out);
}

// round 8
// speedup vs baseline: 2.7247x; 1.2979x over previous
#include <cuda_runtime.h>
#include <cstdint>

#define BN_EPS 1e-5f

// ---------------- device scratch ----------------
// g_pcl stores channels PERMUTED: slot s holds channel ci = (s>>2) + 4*(s&3)
// (4x4 transpose, self-inverse) so K2's per-thread A-regs are one float4.
__device__ float         g_pcl[16 * 256 * 256 * 16];
__device__ float4        g_wf4[36 * 32];   // conv2 B fragments: [tap][nt][lane]
__device__ float4        g_w1f4[6 * 32];   // conv1 B fragments: [ky][nt][lane]
__device__ unsigned char g_mask[256 * 256];
__device__ int           g_count_i;
__device__ float         g_S[16 * 32];
__device__ float         g_bias1[16];
__device__ float         g_bias2[32];

// ---------------- helpers ----------------
__device__ __forceinline__ float rna(float x) {  // round fp32 -> tf32 (RN)
    uint32_t r;
    asm("cvt.rna.tf32.f32 %0, %1;" : "=r"(r) : "f"(x));
    return __uint_as_float(r);
}
__device__ __forceinline__ void mma8(float* d, uint32_t a0, uint32_t a1, uint32_t a2,
                                     uint32_t a3, uint32_t b0, uint32_t b1) {
    asm volatile(
        "mma.sync.aligned.m16n8k8.row.col.f32.tf32.tf32.f32 "
        "{%0,%1,%2,%3},{%4,%5,%6,%7},{%8,%9},{%0,%1,%2,%3};"
        : "+f"(d[0]), "+f"(d[1]), "+f"(d[2]), "+f"(d[3])
        : "r"(a0), "r"(a1), "r"(a2), "r"(a3), "r"(b0), "r"(b1));
}
__device__ __forceinline__ void mma4(float* d, uint32_t a0, uint32_t a1, uint32_t b0) {
    asm volatile(
        "mma.sync.aligned.m16n8k4.row.col.f32.tf32.tf32.f32 "
        "{%0,%1,%2,%3},{%4,%5},{%6},{%0,%1,%2,%3};"
        : "+f"(d[0]), "+f"(d[1]), "+f"(d[2]), "+f"(d[3])
        : "r"(a0), "r"(a1), "r"(b0));
}

// ---------------------------------------------------------------------------
// prep: fold BN, build rounded tf32 weight fragments for both convs.
// ---------------------------------------------------------------------------
__global__ void prep_kernel(const float* __restrict__ w1,
                            const float* __restrict__ g1, const float* __restrict__ b1,
                            const float* __restrict__ m1, const float* __restrict__ v1,
                            const float* __restrict__ w2,
                            const float* __restrict__ g2, const float* __restrict__ b2,
                            const float* __restrict__ m2, const float* __restrict__ v2) {
    int t = threadIdx.x;  // 256
    for (int i = t; i < 512; i += 256) g_S[i] = 0.f;
    if (t == 0) g_count_i = 0;

    if (t < 192) {  // conv1 fragments
        int lane = t & 31, nt = (t >> 5) & 1, ky = t >> 6;
        int g = lane >> 2, tg = lane & 3;
        int n = nt * 8 + g;
        float s = g1[n] * rsqrtf(v1[n] + BN_EPS);
        float r[3];
#pragma unroll
        for (int dx = 0; dx < 3; dx++)
            r[dx] = (tg < 3) ? rna(w1[((n * 3 + tg) * 3 + ky) * 3 + dx] * s) : 0.f;
        g_w1f4[t] = make_float4(r[0], r[1], r[2], 0.f);
    }
    for (int i = t; i < 1152; i += 256) {  // conv2 fragments
        int lane = i & 31, nt = (i >> 5) & 3, tap = i >> 7;
        int g = lane >> 2, tg = lane & 3;
        int ky = tap / 3, kx = tap % 3;
        int n = nt * 8 + g;
        float s = g2[n] * rsqrtf(v2[n] + BN_EPS);
        float4 f;
        f.x = rna(w2[((n * 16 + (tg + 0)) * 3 + ky) * 3 + kx] * s);
        f.y = rna(w2[((n * 16 + (tg + 4)) * 3 + ky) * 3 + kx] * s);
        f.z = rna(w2[((n * 16 + (tg + 8)) * 3 + ky) * 3 + kx] * s);
        f.w = rna(w2[((n * 16 + (tg + 12)) * 3 + ky) * 3 + kx] * s);
        g_wf4[i] = f;
    }
    if (t < 16) {
        float s = g1[t] * rsqrtf(v1[t] + BN_EPS);
        g_bias1[t] = b1[t] - m1[t] * s;
    }
    if (t < 32) {
        float s = g2[t] * rsqrtf(v2[t] + BN_EPS);
        g_bias2[t] = b2[t] - m2[t] * s;
    }
}

// ---------------------------------------------------------------------------
// K1: conv1(3->16)+bn+relu+maxpool via tf32 mma.
// CTA = 128 conv px x 8 conv rows (= 64 x 4 pooled). 8 warps x 16 px, each
// warp does two 4-row groups. Vectorized transpose fill: per 4-px cell group,
// 3 aligned LDG.128 + 4 STS.128. Cell c -> gx = x0 - 4 + c (16B aligned).
// A-frag cell for tile px p, tap dx: c = p + 3 + dx.
// ---------------------------------------------------------------------------
__global__ __launch_bounds__(256) void k1t_kernel(const float* __restrict__ x) {
    __shared__ float  s_a[10 * 136 * 4];    // [row][cell][ci] pitch 4
    __shared__ float4 s_wf[192];
    __shared__ float  s_b[16];
    __shared__ float  s_out[4 * 64 * 16];   // [prow][ppx][slot]

    int b = blockIdx.z, bx = blockIdx.x, by = blockIdx.y;
    int tid = threadIdx.x;

    if (tid < 192) s_wf[tid] = g_w1f4[tid];
    if (tid < 16) s_b[tid] = g_bias1[tid];

    int y0 = by * 8, x0 = bx * 128;
    const float* xb = x + (size_t)b * 3 * 262144;
    for (int t = tid; t < 340; t += 256) {  // 10 rows x 34 groups
        int r = t / 34, j = t % 34;
        int gy = y0 - 1 + r;
        int gxb = x0 - 4 + 4 * j;
        float4 va = {0.f, 0.f, 0.f, 0.f}, vb = va, vc = va;
        if ((unsigned)gy < 512u) {
            const float* row0 = xb + (size_t)gy * 512;
            if (gxb >= 0 && gxb + 3 < 512) {
                va = *(const float4*)(row0 + gxb);
                vb = *(const float4*)(row0 + 262144 + gxb);
                vc = *(const float4*)(row0 + 524288 + gxb);
            } else {
#pragma unroll
                for (int l = 0; l < 4; l++) {
                    int gx = gxb + l;
                    if ((unsigned)gx < 512u) {
                        (&va.x)[l] = row0[gx];
                        (&vb.x)[l] = row0[262144 + gx];
                        (&vc.x)[l] = row0[524288 + gx];
                    }
                }
            }
        }
        float4* dst = (float4*)(s_a + (r * 136 + 4 * j) * 4);
        dst[0] = make_float4(rna(va.x), rna(vb.x), rna(vc.x), 0.f);
        dst[1] = make_float4(rna(va.y), rna(vb.y), rna(vc.y), 0.f);
        dst[2] = make_float4(rna(va.z), rna(vb.z), rna(vc.z), 0.f);
        dst[3] = make_float4(rna(va.w), rna(vb.w), rna(vc.w), 0.f);
    }
    __syncthreads();

    int w = tid >> 5, lane = tid & 31, g = lane >> 2, tg = lane & 3;
    int cb = w * 16 + g;

#pragma unroll
    for (int rg = 0; rg < 2; rg++) {
        uint32_t A[6][3][2];  // [row][dx][half]
#pragma unroll
        for (int rr = 0; rr < 6; rr++)
#pragma unroll
            for (int dx = 0; dx < 3; dx++) {
                int rowb = (rg * 4 + rr) * 136;
                A[rr][dx][0] = __float_as_uint(s_a[(rowb + cb + 3 + dx) * 4 + tg]);
                A[rr][dx][1] = __float_as_uint(s_a[(rowb + cb + 11 + dx) * 4 + tg]);
            }

        float d[4][2][4];
#pragma unroll
        for (int r = 0; r < 4; r++)
#pragma unroll
            for (int nt = 0; nt < 2; nt++)
#pragma unroll
                for (int j = 0; j < 4; j++) d[r][nt][j] = 0.f;

#pragma unroll
        for (int ky = 0; ky < 3; ky++)
#pragma unroll
            for (int nt = 0; nt < 2; nt++) {
                float4 wv = s_wf[(ky * 2 + nt) * 32 + lane];
                uint32_t b0 = __float_as_uint(wv.x);
                uint32_t b1 = __float_as_uint(wv.y);
                uint32_t b2 = __float_as_uint(wv.z);
#pragma unroll
                for (int r = 0; r < 4; r++) {
                    int ri = r + ky;
                    mma8(d[r][nt], A[ri][0][0], A[ri][0][1], A[ri][1][0], A[ri][1][1],
                         b0, b1);
                    mma4(d[r][nt], A[ri][2][0], A[ri][2][1], b2);
                }
            }

        // maxpool 2x2 + bias + relu + tf32-round, stage channels-permuted
#pragma unroll
        for (int q = 0; q < 2; q++)
#pragma unroll
            for (int nt = 0; nt < 2; nt++) {
                float m[4];
#pragma unroll
                for (int j = 0; j < 4; j++) {
                    float mm = fmaxf(d[2 * q][nt][j], d[2 * q + 1][nt][j]);
                    mm = fmaxf(mm, __shfl_xor_sync(0xffffffffu, mm, 4));
                    m[j] = mm;
                }
                if (!(g & 1)) {
                    int j = g >> 1;
                    int co0 = nt * 8 + 2 * tg, co1 = co0 + 1;
                    int sl0 = (co0 & 3) * 4 + (co0 >> 2);
                    int sl1 = (co1 & 3) * 4 + (co1 >> 2);
                    int base0 = ((rg * 2 + q) * 64 + w * 8 + j) * 16;
                    int base1 = ((rg * 2 + q) * 64 + w * 8 + j + 4) * 16;
                    s_out[base0 + sl0] = rna(fmaxf(m[0] + s_b[co0], 0.f));
                    s_out[base0 + sl1] = rna(fmaxf(m[1] + s_b[co1], 0.f));
                    s_out[base1 + sl0] = rna(fmaxf(m[2] + s_b[co0], 0.f));
                    s_out[base1 + sl1] = rna(fmaxf(m[3] + s_b[co1], 0.f));
                }
            }
    }
    __syncthreads();

    for (int idx = tid; idx < 1024; idx += 256) {
        int prow = idx >> 8, rem = idx & 255, ppx = rem >> 2, s4 = rem & 3;
        int py = by * 4 + prow, pxg = bx * 64 + ppx;
        ((float4*)(g_pcl + ((size_t)(b * 256 + py) * 256 + pxg) * 16))[s4] =
            ((const float4*)s_out)[idx];
    }
}

// ---------------------------------------------------------------------------
// K2: conv2(16->32)+bn+relu via tf32 mma. CTA = full row (256 px), 8 warps
// x 32 px (2 m-tiles). A: 3 rows x 258 cells x 16 floats, pitch 16.
// MODE 0: batch 0 -> mask + count.  MODE 1: masked channel sums.
// ---------------------------------------------------------------------------
#define K2_SA_F   (3 * 258 * 16)          // 12384 floats
#define K2_WF_F   K2_SA_F
#define K2_BIAS_F (K2_SA_F + 4608)        // 16992
#define K2_PF_F   (K2_BIAS_F + 32)
#define K2_RED_F  (K2_PF_F + 32)
#define K2_TOT_F  (K2_RED_F + 256)        // 17312
#define K2_SMEM   (K2_TOT_F * 4)          // 69248 B

template <int MODE>
__global__ __launch_bounds__(256) void k2_kernel(const float* __restrict__ pf_w,
                                                 const float* __restrict__ pf_b) {
    extern __shared__ float sm[];
    float*  s_A    = sm;
    float4* s_wf   = (float4*)(sm + K2_WF_F);
    float*  s_bias = sm + K2_BIAS_F;
    float*  s_pf   = sm + K2_PF_F;
    float*  s_red  = sm + K2_RED_F;

    int tid = threadIdx.x;
    int y = blockIdx.x;
    int b = (MODE == 0) ? 0 : blockIdx.y;

    for (int i = tid; i < 1152; i += 256) s_wf[i] = g_wf4[i];
    if (tid < 32) {
        s_bias[tid] = g_bias2[tid];
        s_pf[tid] = pf_w[tid];
    }

    for (int i = tid; i < 3096; i += 256) {
        int row = i / 1032, rem = i % 1032, cell = rem >> 2, j = rem & 3;
        int yy = y - 1 + row;
        float4 v = make_float4(0.f, 0.f, 0.f, 0.f);
        if ((unsigned)yy < 256u && cell >= 1 && cell <= 256)
            v = ((const float4*)(g_pcl +
                                 ((size_t)(b * 256 + yy) * 256 + (cell - 1)) * 16))[j];
        ((float4*)s_A)[i] = v;
    }
    __syncthreads();

    int w = tid >> 5, lane = tid & 31, g = lane >> 2, tg = lane & 3;
    int pxb = w * 32;

    float d[2][4][4];
#pragma unroll
    for (int mt = 0; mt < 2; mt++)
#pragma unroll
        for (int nt = 0; nt < 4; nt++)
#pragma unroll
            for (int j = 0; j < 4; j++) d[mt][nt][j] = 0.f;

#pragma unroll
    for (int ky = 0; ky < 3; ky++)
#pragma unroll
        for (int kx = 0; kx < 3; kx++) {
            int tap = ky * 3 + kx;
            float4 av0[2], av1[2];
#pragma unroll
            for (int mt = 0; mt < 2; mt++) {
                int cell = pxb + mt * 16 + g + kx;
                av0[mt] = ((const float4*)(s_A + (ky * 258 + cell) * 16))[tg];
                av1[mt] = ((const float4*)(s_A + (ky * 258 + cell + 8) * 16))[tg];
            }
#pragma unroll
            for (int nt = 0; nt < 4; nt++) {
                float4 bv = s_wf[(tap * 4 + nt) * 32 + lane];
                uint32_t b00 = __float_as_uint(bv.x), b01 = __float_as_uint(bv.y);
                uint32_t b10 = __float_as_uint(bv.z), b11 = __float_as_uint(bv.w);
#pragma unroll
                for (int mt = 0; mt < 2; mt++) {
                    mma8(d[mt][nt], __float_as_uint(av0[mt].x), __float_as_uint(av1[mt].x),
                         __float_as_uint(av0[mt].y), __float_as_uint(av1[mt].y), b00, b01);
                    mma8(d[mt][nt], __float_as_uint(av0[mt].z), __float_as_uint(av1[mt].z),
                         __float_as_uint(av0[mt].w), __float_as_uint(av1[mt].w), b10, b11);
                }
            }
        }

    if (MODE == 0) {
        float s[2][2] = {{0.f, 0.f}, {0.f, 0.f}};
#pragma unroll
        for (int mt = 0; mt < 2; mt++)
#pragma unroll
            for (int nt = 0; nt < 4; nt++) {
                float b0n = s_bias[nt * 8 + 2 * tg], b1n = s_bias[nt * 8 + 2 * tg + 1];
                float p0n = s_pf[nt * 8 + 2 * tg], p1n = s_pf[nt * 8 + 2 * tg + 1];
                s[mt][0] += fmaxf(d[mt][nt][0] + b0n, 0.f) * p0n +
                            fmaxf(d[mt][nt][1] + b1n, 0.f) * p1n;
                s[mt][1] += fmaxf(d[mt][nt][2] + b0n, 0.f) * p0n +
                            fmaxf(d[mt][nt][3] + b1n, 0.f) * p1n;
            }
#pragma unroll
        for (int mt = 0; mt < 2; mt++)
#pragma unroll
            for (int h = 0; h < 2; h++) {
                s[mt][h] += __shfl_xor_sync(0xffffffffu, s[mt][h], 1);
                s[mt][h] += __shfl_xor_sync(0xffffffffu, s[mt][h], 2);
            }
        int cnt = 0;
        if (tg == 0) {
            float pb = pf_b[0];
#pragma unroll
            for (int mt = 0; mt < 2; mt++) {
                int px = pxb + mt * 16 + g;
                unsigned char m0 = (s[mt][0] + pb) > 0.f;
                unsigned char m1 = (s[mt][1] + pb) > 0.f;
                g_mask[y * 256 + px] = m0;
                g_mask[y * 256 + px + 8] = m1;
                cnt += m0 + m1;
            }
        }
        cnt = __reduce_add_sync(0xffffffffu, cnt);
        if (lane == 0) atomicAdd(&g_count_i, cnt);
    } else {
        float part[4][2];
#pragma unroll
        for (int nt = 0; nt < 4; nt++) { part[nt][0] = 0.f; part[nt][1] = 0.f; }
#pragma unroll
        for (int mt = 0; mt < 2; mt++) {
            float mA = (float)g_mask[y * 256 + pxb + mt * 16 + g];
            float mB = (float)g_mask[y * 256 + pxb + mt * 16 + g + 8];
#pragma unroll
            for (int nt = 0; nt < 4; nt++) {
                float b0n = s_bias[nt * 8 + 2 * tg], b1n = s_bias[nt * 8 + 2 * tg + 1];
                part[nt][0] += mA * fmaxf(d[mt][nt][0] + b0n, 0.f) +
                               mB * fmaxf(d[mt][nt][2] + b0n, 0.f);
                part[nt][1] += mA * fmaxf(d[mt][nt][1] + b1n, 0.f) +
                               mB * fmaxf(d[mt][nt][3] + b1n, 0.f);
            }
        }
#pragma unroll
        for (int nt = 0; nt < 4; nt++)
#pragma unroll
            for (int h = 0; h < 2; h++) {
#pragma unroll
                for (int off = 4; off <= 16; off <<= 1)
                    part[nt][h] += __shfl_xor_sync(0xffffffffu, part[nt][h], off);
            }
        if (g == 0) {
#pragma unroll
            for (int nt = 0; nt < 4; nt++) {
                s_red[w * 32 + nt * 8 + 2 * tg] = part[nt][0];
                s_red[w * 32 + nt * 8 + 2 * tg + 1] = part[nt][1];
            }
        }
        __syncthreads();
        if (tid < 32) {
            float s = 0.f;
#pragma unroll
            for (int ww = 0; ww < 8; ww++) s += s_red[ww * 32 + tid];
            atomicAdd(&g_S[b * 32 + tid], s);
        }
    }
}

// ---------------------------------------------------------------------------
__global__ void k3_kernel(const float* __restrict__ vw, const float* __restrict__ vb,
                          const float* __restrict__ cw, const float* __restrict__ cb,
                          float* __restrict__ out) {
    __shared__ float s_mean[512];
    __shared__ float s_cm[1280];
    int t = threadIdx.x;  // 256
    int cnt = g_count_i;
    float denom = (float)(cnt > 0 ? cnt : 1);
    float frac = cnt > 0 ? 1.f : 0.f;
    for (int i = t; i < 512; i += 256) s_mean[i] = g_S[i] / denom;
    __syncthreads();
    for (int i = t; i < 16 * 80; i += 256) {
        int b = i / 80, k = i % 80;
        float a = vb[k] * frac;
        const float* wm = vw + k * 32;
        const float* mm = s_mean + b * 32;
#pragma unroll
        for (int c = 0; c < 32; c++) a += mm[c] * wm[c];
        s_cm[i] = a;
    }
    __syncthreads();
    for (int i = t; i < 1280; i += 256) {
        int b = i / 80, j = i % 80;
        float a = cb[j];
        const float* w = cw + j * 80;
        const float* m = s_cm + b * 80;
#pragma unroll
        for (int k = 0; k < 80; k++) a += m[k] * w[k];
        out[i] = a;
    }
}

// ---------------------------------------------------------------------------
extern "C" void kernel_launch(void* const* d_in, const int* in_sizes, int n_in,
                              void* d_out, int out_size) {
    const float* x   = (const float*)d_in[0];
    const float* w1  = (const float*)d_in[1];
    const float* g1  = (const float*)d_in[2];
    const float* b1  = (const float*)d_in[3];
    const float* m1  = (const float*)d_in[4];
    const float* v1  = (const float*)d_in[5];
    const float* w2  = (const float*)d_in[6];
    const float* g2  = (const float*)d_in[7];
    const float* b2  = (const float*)d_in[8];
    const float* m2  = (const float*)d_in[9];
    const float* v2  = (const float*)d_in[10];
    const float* pfw = (const float*)d_in[11];
    const float* pfb = (const float*)d_in[12];
    const float* vw  = (const float*)d_in[13];
    const float* vb  = (const float*)d_in[14];
    const float* cw  = (const float*)d_in[15];
    const float* cb  = (const float*)d_in[16];
    float* out = (float*)d_out;

    cudaFuncSetAttribute(k2_kernel<0>, cudaFuncAttributeMaxDynamicSharedMemorySize,
                         K2_SMEM);
    cudaFuncSetAttribute(k2_kernel<1>, cudaFuncAttributeMaxDynamicSharedMemorySize,
                         K2_SMEM);

    prep_kernel<<<1, 256>>>(w1, g1, b1, m1, v1, w2, g2, b2, m2, v2);
    k1t_kernel<<<dim3(4, 64, 16), 256>>>(x);
    k2_kernel<0><<<dim3(256, 1, 1), 256, K2_SMEM>>>(pfw, pfb);
    k2_kernel<1><<<dim3(256, 16, 1), 256, K2_SMEM>>>(pfw, pfb);
    k3_kernel<<<1, 256>>>(vw, vb, cw, cb, out);
}

// round 10
// speedup vs baseline: 4.1467x; 1.5219x over previous
#include <cuda_runtime.h>
#include <cuda_fp16.h>
#include <cstdint>

#define BN_EPS 1e-5f

// ---------------- device scratch ----------------
// g_pclh: fp16 channels-last, channel ci stored at slot sigma(ci):
//   ci<8 : (ci>>1)*4 + (ci&1)
//   ci>=8: ((ci-8)>>1)*4 + 2 + (ci&1)
// so per-thread fp16 MMA fragment halves {2tg,2tg+1,2tg+8,2tg+9} = one 8B word.
__device__ __half        g_pclh[16 * 256 * 256 * 16];
__device__ uint2         g_w2h[9 * 4 * 32];   // conv2 B fragments [tap][nt][lane]
__device__ uint2         g_w1h[3 * 2 * 32];   // conv1 B fragments [ky][nt][lane]
__device__ unsigned char g_mask[256 * 256];
__device__ int           g_count_i;
__device__ float         g_S[16 * 32];
__device__ float         g_bias1[16];
__device__ float         g_bias2[32];

// ---------------- helpers ----------------
__device__ __forceinline__ uint32_t pack2h(float a, float b) {
    __half2 h = __floats2half2_rn(a, b);
    return *(uint32_t*)&h;
}
__device__ __forceinline__ void mma16(float* d, uint32_t a0, uint32_t a1, uint32_t a2,
                                      uint32_t a3, uint32_t b0, uint32_t b1) {
    asm volatile(
        "mma.sync.aligned.m16n8k16.row.col.f32.f16.f16.f32 "
        "{%0,%1,%2,%3},{%4,%5,%6,%7},{%8,%9},{%0,%1,%2,%3};"
        : "+f"(d[0]), "+f"(d[1]), "+f"(d[2]), "+f"(d[3])
        : "r"(a0), "r"(a1), "r"(a2), "r"(a3), "r"(b0), "r"(b1));
}

// ---------------------------------------------------------------------------
// prep: fold BN, build fp16 B-fragments for both convs.
// fp16 m16n8k16 B frag (K16 x N8 col-major), lane (g=lane>>2, tg=lane&3):
//   b0 = {B[2tg][g], B[2tg+1][g]},  b1 = {B[2tg+8][g], B[2tg+9][g]}
// conv1 K index k = dx*4+ci (ci<3, dx<3 valid; else 0). conv2 k = ci.
// ---------------------------------------------------------------------------
__global__ void prep_kernel(const float* __restrict__ w1,
                            const float* __restrict__ g1, const float* __restrict__ b1,
                            const float* __restrict__ m1, const float* __restrict__ v1,
                            const float* __restrict__ w2,
                            const float* __restrict__ g2, const float* __restrict__ b2,
                            const float* __restrict__ m2, const float* __restrict__ v2) {
    int t = threadIdx.x;  // 256
    for (int i = t; i < 512; i += 256) g_S[i] = 0.f;
    if (t == 0) g_count_i = 0;

    if (t < 192) {  // conv1 fragments
        int lane = t & 31, nt = (t >> 5) & 1, ky = t >> 6;
        int g = lane >> 2, tg = lane & 3;
        int n = nt * 8 + g;
        float s = g1[n] * rsqrtf(v1[n] + BN_EPS);
        auto wk = [&](int k) -> float {
            int dx = k >> 2, ci = k & 3;
            return (ci < 3 && dx < 3) ? w1[((n * 3 + ci) * 3 + ky) * 3 + dx] * s : 0.f;
        };
        g_w1h[t] = make_uint2(pack2h(wk(2 * tg), wk(2 * tg + 1)),
                              pack2h(wk(2 * tg + 8), wk(2 * tg + 9)));
    }
    for (int i = t; i < 1152; i += 256) {  // conv2 fragments
        int lane = i & 31, nt = (i >> 5) & 3, tap = i >> 7;
        int g = lane >> 2, tg = lane & 3;
        int ky = tap / 3, kx = tap % 3;
        int n = nt * 8 + g;
        float s = g2[n] * rsqrtf(v2[n] + BN_EPS);
        auto wc = [&](int ci) -> float {
            return w2[((n * 16 + ci) * 3 + ky) * 3 + kx] * s;
        };
        g_w2h[i] = make_uint2(pack2h(wc(2 * tg), wc(2 * tg + 1)),
                              pack2h(wc(2 * tg + 8), wc(2 * tg + 9)));
    }
    if (t < 16) {
        float s = g1[t] * rsqrtf(v1[t] + BN_EPS);
        g_bias1[t] = b1[t] - m1[t] * s;
    }
    if (t < 32) {
        float s = g2[t] * rsqrtf(v2[t] + BN_EPS);
        g_bias2[t] = b2[t] - m2[t] * s;
    }
}

// ---------------------------------------------------------------------------
// K1: conv1(3->16)+bn+relu+maxpool via fp16 mma (K16 = 3dx x 4ci lin im2col).
// CTA = 128 conv px x 8 conv rows (= 64 x 4 pooled). 8 warps x 16 px x 2 rgs.
// smem A: [10 rows][136 cells][4 halves]; fill = 3 LDG.128 + 2 STS.128 / 4px.
// ---------------------------------------------------------------------------
__global__ __launch_bounds__(256) void k1t_kernel(const float* __restrict__ x) {
    __shared__ __align__(16) __half s_a[10 * 136 * 4];
    __shared__ uint2  s_wf[192];
    __shared__ float  s_b[16];
    __shared__ __align__(16) __half s_out[4 * 64 * 16];

    int b = blockIdx.z, bx = blockIdx.x, by = blockIdx.y;
    int tid = threadIdx.x;

    if (tid < 192) s_wf[tid] = g_w1h[tid];
    if (tid < 16) s_b[tid] = g_bias1[tid];

    int y0 = by * 8, x0 = bx * 128;
    const float* xb = x + (size_t)b * 3 * 262144;
    for (int t = tid; t < 340; t += 256) {  // 10 rows x 34 groups of 4 px
        int r = t / 34, j = t % 34;
        int gy = y0 - 1 + r;
        int gxb = x0 - 4 + 4 * j;
        float4 va = {0.f, 0.f, 0.f, 0.f}, vb = va, vc = va;
        if ((unsigned)gy < 512u) {
            const float* row0 = xb + (size_t)gy * 512;
            if (gxb >= 0 && gxb + 3 < 512) {
                va = *(const float4*)(row0 + gxb);
                vb = *(const float4*)(row0 + 262144 + gxb);
                vc = *(const float4*)(row0 + 524288 + gxb);
            } else {
#pragma unroll
                for (int l = 0; l < 4; l++) {
                    int gx = gxb + l;
                    if ((unsigned)gx < 512u) {
                        (&va.x)[l] = row0[gx];
                        (&vb.x)[l] = row0[262144 + gx];
                        (&vc.x)[l] = row0[524288 + gx];
                    }
                }
            }
        }
        uint4* dst = (uint4*)(s_a + (size_t)(r * 136 + 4 * j) * 4);
        uint4 p0, p1;
        p0.x = pack2h(va.x, vb.x); p0.y = pack2h(vc.x, 0.f);
        p0.z = pack2h(va.y, vb.y); p0.w = pack2h(vc.y, 0.f);
        p1.x = pack2h(va.z, vb.z); p1.y = pack2h(vc.z, 0.f);
        p1.z = pack2h(va.w, vb.w); p1.w = pack2h(vc.w, 0.f);
        dst[0] = p0;
        dst[1] = p1;
    }
    __syncthreads();

    int w = tid >> 5, lane = tid & 31, g = lane >> 2, tg = lane & 3;
    int cb = w * 16 + g + 3;
    const uint32_t* s_au = (const uint32_t*)s_a;

#pragma unroll
    for (int rg = 0; rg < 2; rg++) {
        uint32_t A[6][4];  // [row][a0,a1,a2,a3]
#pragma unroll
        for (int rr = 0; rr < 6; rr++) {
            int base = ((rg * 4 + rr) * 136 + cb) * 2;
            A[rr][0] = s_au[base + tg];
            A[rr][1] = s_au[base + 16 + tg];
            A[rr][2] = s_au[base + tg + 4];
            A[rr][3] = s_au[base + 16 + tg + 4];
        }

        float d[4][2][4];
#pragma unroll
        for (int r = 0; r < 4; r++)
#pragma unroll
            for (int nt = 0; nt < 2; nt++)
#pragma unroll
                for (int j = 0; j < 4; j++) d[r][nt][j] = 0.f;

#pragma unroll
        for (int ky = 0; ky < 3; ky++)
#pragma unroll
            for (int nt = 0; nt < 2; nt++) {
                uint2 wv = s_wf[(ky * 2 + nt) * 32 + lane];
#pragma unroll
                for (int r = 0; r < 4; r++) {
                    int ri = r + ky;
                    mma16(d[r][nt], A[ri][0], A[ri][1], A[ri][2], A[ri][3], wv.x, wv.y);
                }
            }

        // maxpool 2x2 + bias + relu, stage fp16 channels-permuted
#pragma unroll
        for (int q = 0; q < 2; q++)
#pragma unroll
            for (int nt = 0; nt < 2; nt++) {
                float m[4];
#pragma unroll
                for (int j = 0; j < 4; j++) {
                    float mm = fmaxf(d[2 * q][nt][j], d[2 * q + 1][nt][j]);
                    mm = fmaxf(mm, __shfl_xor_sync(0xffffffffu, mm, 4));
                    m[j] = mm;
                }
                if (!(g & 1)) {
                    int j = g >> 1;
                    int sl0 = tg * 4 + nt * 2;       // sigma(nt*8+2tg)
                    int sl1 = sl0 + 1;                // sigma(nt*8+2tg+1)
                    float b0 = s_b[nt * 8 + 2 * tg], b1 = s_b[nt * 8 + 2 * tg + 1];
                    int base0 = ((rg * 2 + q) * 64 + w * 8 + j) * 16;
                    int base1 = ((rg * 2 + q) * 64 + w * 8 + j + 4) * 16;
                    s_out[base0 + sl0] = __float2half_rn(fmaxf(m[0] + b0, 0.f));
                    s_out[base0 + sl1] = __float2half_rn(fmaxf(m[1] + b1, 0.f));
                    s_out[base1 + sl0] = __float2half_rn(fmaxf(m[2] + b0, 0.f));
                    s_out[base1 + sl1] = __float2half_rn(fmaxf(m[3] + b1, 0.f));
                }
            }
    }
    __syncthreads();

    for (int idx = tid; idx < 512; idx += 256) {  // 512 x 16B
        int s2 = idx & 1, ppx = (idx >> 1) & 63, prow = idx >> 7;
        int py = by * 4 + prow, pxg = bx * 64 + ppx;
        ((uint4*)(g_pclh + ((size_t)(b * 256 + py) * 256 + pxg) * 16))[s2] =
            ((const uint4*)s_out)[idx];
    }
}

// ---------------------------------------------------------------------------
// K2: conv2(16->32)+bn+relu via fp16 mma. CTA = full row (256 px), 8 warps
// x 32 px (2 m-tiles). A: 3 rows x 258 cells x 16 halves (32B/cell).
// Fragment loads are LDS.64, conflict-free per 16-lane phase.
// MODE 0: batch 0 -> mask + count.  MODE 1: masked channel sums.
// ---------------------------------------------------------------------------
template <int MODE>
__global__ __launch_bounds__(256) void k2_kernel(const float* __restrict__ pf_w,
                                                 const float* __restrict__ pf_b) {
    __shared__ __align__(16) __half s_A[3 * 258 * 16];  // 24768 B
    __shared__ uint2  s_wf[1152];                        // 9216 B
    __shared__ float  s_bias[32];
    __shared__ float  s_pf[32];
    __shared__ float  s_red[256];

    int tid = threadIdx.x;
    int y = blockIdx.x;
    int b = (MODE == 0) ? 0 : blockIdx.y;

    for (int i = tid; i < 1152; i += 256) s_wf[i] = g_w2h[i];
    if (tid < 32) {
        s_bias[tid] = g_bias2[tid];
        s_pf[tid] = pf_w[tid];
    }

    // A fill: rows y-1..y+1, cells 0..257 (px = cell-1), 2 uint4 per cell
    for (int i = tid; i < 1548; i += 256) {
        int row = i / 516, rem = i % 516, cell = rem >> 1, hi = rem & 1;
        int yy = y - 1 + row, px = cell - 1;
        uint4 v = {0u, 0u, 0u, 0u};
        if ((unsigned)yy < 256u && (unsigned)px < 256u)
            v = ((const uint4*)(g_pclh + ((size_t)(b * 256 + yy) * 256 + px) * 16))[hi];
        ((uint4*)s_A)[i] = v;
    }
    __syncthreads();

    int w = tid >> 5, lane = tid & 31, g = lane >> 2, tg = lane & 3;
    int pxb = w * 32;
    const uint32_t* s_Au = (const uint32_t*)s_A;

    float d[2][4][4];
#pragma unroll
    for (int mt = 0; mt < 2; mt++)
#pragma unroll
        for (int nt = 0; nt < 4; nt++)
#pragma unroll
            for (int j = 0; j < 4; j++) d[mt][nt][j] = 0.f;

#pragma unroll
    for (int ky = 0; ky < 3; ky++)
#pragma unroll
        for (int kx = 0; kx < 3; kx++) {
            int tap = ky * 3 + kx;
            uint2 a02[2], a13[2];
#pragma unroll
            for (int mt = 0; mt < 2; mt++) {
                int cell = pxb + mt * 16 + g + kx;
                int cb8 = (ky * 258 + cell) * 8;
                a02[mt] = *(const uint2*)(s_Au + cb8 + 2 * tg);
                a13[mt] = *(const uint2*)(s_Au + cb8 + 64 + 2 * tg);
            }
#pragma unroll
            for (int nt = 0; nt < 4; nt++) {
                uint2 wv = s_wf[(tap * 4 + nt) * 32 + lane];
#pragma unroll
                for (int mt = 0; mt < 2; mt++)
                    mma16(d[mt][nt], a02[mt].x, a13[mt].x, a02[mt].y, a13[mt].y,
                          wv.x, wv.y);
            }
        }

    if (MODE == 0) {
        float s[2][2] = {{0.f, 0.f}, {0.f, 0.f}};
#pragma unroll
        for (int mt = 0; mt < 2; mt++)
#pragma unroll
            for (int nt = 0; nt < 4; nt++) {
                float b0n = s_bias[nt * 8 + 2 * tg], b1n = s_bias[nt * 8 + 2 * tg + 1];
                float p0n = s_pf[nt * 8 + 2 * tg], p1n = s_pf[nt * 8 + 2 * tg + 1];
                s[mt][0] += fmaxf(d[mt][nt][0] + b0n, 0.f) * p0n +
                            fmaxf(d[mt][nt][1] + b1n, 0.f) * p1n;
                s[mt][1] += fmaxf(d[mt][nt][2] + b0n, 0.f) * p0n +
                            fmaxf(d[mt][nt][3] + b1n, 0.f) * p1n;
            }
#pragma unroll
        for (int mt = 0; mt < 2; mt++)
#pragma unroll
            for (int h = 0; h < 2; h++) {
                s[mt][h] += __shfl_xor_sync(0xffffffffu, s[mt][h], 1);
                s[mt][h] += __shfl_xor_sync(0xffffffffu, s[mt][h], 2);
            }
        int cnt = 0;
        if (tg == 0) {
            float pb = pf_b[0];
#pragma unroll
            for (int mt = 0; mt < 2; mt++) {
                int px = pxb + mt * 16 + g;
                unsigned char m0 = (s[mt][0] + pb) > 0.f;
                unsigned char m1 = (s[mt][1] + pb) > 0.f;
                g_mask[y * 256 + px] = m0;
                g_mask[y * 256 + px + 8] = m1;
                cnt += m0 + m1;
            }
        }
        cnt = __reduce_add_sync(0xffffffffu, cnt);
        if (lane == 0) atomicAdd(&g_count_i, cnt);
    } else {
        float part[4][2];
#pragma unroll
        for (int nt = 0; nt < 4; nt++) { part[nt][0] = 0.f; part[nt][1] = 0.f; }
#pragma unroll
        for (int mt = 0; mt < 2; mt++) {
            float mA = (float)g_mask[y * 256 + pxb + mt * 16 + g];
            float mB = (float)g_mask[y * 256 + pxb + mt * 16 + g + 8];
#pragma unroll
            for (int nt = 0; nt < 4; nt++) {
                float b0n = s_bias[nt * 8 + 2 * tg], b1n = s_bias[nt * 8 + 2 * tg + 1];
                part[nt][0] += mA * fmaxf(d[mt][nt][0] + b0n, 0.f) +
                               mB * fmaxf(d[mt][nt][2] + b0n, 0.f);
                part[nt][1] += mA * fmaxf(d[mt][nt][1] + b1n, 0.f) +
                               mB * fmaxf(d[mt][nt][3] + b1n, 0.f);
            }
        }
#pragma unroll
        for (int nt = 0; nt < 4; nt++)
#pragma unroll
            for (int h = 0; h < 2; h++) {
#pragma unroll
                for (int off = 4; off <= 16; off <<= 1)
                    part[nt][h] += __shfl_xor_sync(0xffffffffu, part[nt][h], off);
            }
        if (g == 0) {
#pragma unroll
            for (int nt = 0; nt < 4; nt++) {
                s_red[w * 32 + nt * 8 + 2 * tg] = part[nt][0];
                s_red[w * 32 + nt * 8 + 2 * tg + 1] = part[nt][1];
            }
        }
        __syncthreads();
        if (tid < 32) {
            float s = 0.f;
#pragma unroll
            for (int ww = 0; ww < 8; ww++) s += s_red[ww * 32 + tid];
            atomicAdd(&g_S[b * 32 + tid], s);
        }
    }
}

// ---------------------------------------------------------------------------
__global__ void k3_kernel(const float* __restrict__ vw, const float* __restrict__ vb,
                          const float* __restrict__ cw, const float* __restrict__ cb,
                          float* __restrict__ out) {
    __shared__ float s_mean[512];
    __shared__ float s_cm[1280];
    int t = threadIdx.x;  // 256
    int cnt = g_count_i;
    float denom = (float)(cnt > 0 ? cnt : 1);
    float frac = cnt > 0 ? 1.f : 0.f;
    for (int i = t; i < 512; i += 256) s_mean[i] = g_S[i] / denom;
    __syncthreads();
    for (int i = t; i < 16 * 80; i += 256) {
        int b = i / 80, k = i % 80;
        float a = vb[k] * frac;
        const float* wm = vw + k * 32;
        const float* mm = s_mean + b * 32;
#pragma unroll
        for (int c = 0; c < 32; c++) a += mm[c] * wm[c];
        s_cm[i] = a;
    }
    __syncthreads();
    for (int i = t; i < 1280; i += 256) {
        int b = i / 80, j = i % 80;
        float a = cb[j];
        const float* w = cw + j * 80;
        const float* m = s_cm + b * 80;
#pragma unroll
        for (int k = 0; k < 80; k++) a += m[k] * w[k];
        out[i] = a;
    }
}

// ---------------------------------------------------------------------------
extern "C" void kernel_launch(void* const* d_in, const int* in_sizes, int n_in,
                              void* d_out, int out_size) {
    const float* x   = (const float*)d_in[0];
    const float* w1  = (const float*)d_in[1];
    const float* g1  = (const float*)d_in[2];
    const float* b1  = (const float*)d_in[3];
    const float* m1  = (const float*)d_in[4];
    const float* v1  = (const float*)d_in[5];
    const float* w2  = (const float*)d_in[6];
    const float* g2  = (const float*)d_in[7];
    const float* b2  = (const float*)d_in[8];
    const float* m2  = (const float*)d_in[9];
    const float* v2  = (const float*)d_in[10];
    const float* pfw = (const float*)d_in[11];
    const float* pfb = (const float*)d_in[12];
    const float* vw  = (const float*)d_in[13];
    const float* vb  = (const float*)d_in[14];
    const float* cw  = (const float*)d_in[15];
    const float* cb  = (const float*)d_in[16];
    float* out = (float*)d_out;

    prep_kernel<<<1, 256>>>(w1, g1, b1, m1, v1, w2, g2, b2, m2, v2);
    k1t_kernel<<<dim3(4, 64, 16), 256>>>(x);
    k2_kernel<0><<<dim3(256, 1, 1), 256>>>(pfw, pfb);
    k2_kernel<1><<<dim3(256, 16, 1), 256>>>(pfw, pfb);
    k3_kernel<<<1, 256>>>(vw, vb, cw, cb, out);
}